// round 1
// baseline (speedup 1.0000x reference)
#include <cuda_runtime.h>

// Problem constants
#define Bn 4
#define Tn 2048
#define Cn 1024
#define Hn 16
#define Dn 64

// Scratch (allocation-free rule: __device__ globals)
__device__ float g_q[Bn*Hn*Tn*Dn];    // [B*H, T, D]
__device__ float g_k[Bn*Hn*Tn*Dn];
__device__ float g_v[Bn*Hn*Tn*Dn];
__device__ float g_att[Bn*Tn*Cn];     // attention output, already [B, T, H*D]

// ---------------------------------------------------------------------------
// Kernel 1: QKV projection.  q[b,h,t,d] = sum_c x[b,t,c] * w[h,c,d]
// Grid: (T/128, B*H, 3). Block: 256 threads. Tile: 128(M) x 64(N), BK=16.
// Per-thread micro-tile 8x4.
// ---------------------------------------------------------------------------
__global__ __launch_bounds__(256, 2) void qkv_kernel(
    const float* __restrict__ x,
    const float* __restrict__ wq,
    const float* __restrict__ wk,
    const float* __restrict__ wv)
{
    __shared__ float AsT[16][132];  // k-major x tile (transposed), padded
    __shared__ float Bs[16][64];    // w tile

    const int tid = threadIdx.x;
    const int qt  = blockIdx.x;          // 128-row tile of T
    const int bh  = blockIdx.y;          // b*H + h
    const int p   = blockIdx.z;          // 0=q,1=k,2=v
    const int b   = bh >> 4;
    const int h   = bh & 15;

    const float* w = (p == 0 ? wq : (p == 1 ? wk : wv)) + (size_t)h * Cn * Dn;
    float* outp = (p == 0 ? g_q : (p == 1 ? g_k : g_v))
                  + (size_t)bh * Tn * Dn + (size_t)qt * 128 * Dn;
    const float* xb = x + (size_t)b * Tn * Cn + (size_t)qt * 128 * Cn;

    const int ty = tid >> 4;   // 0..15 -> rows ty*8..+7
    const int tx = tid & 15;   // 0..15 -> cols tx*4..+3

    float acc[8][4] = {};

    for (int k0 = 0; k0 < Cn; k0 += 16) {
        // Load x tile 128x16 -> transposed AsT[k][m]
        #pragma unroll
        for (int i = 0; i < 2; i++) {
            int idx = tid + i * 256;          // 0..511 float4 slots
            int row = idx >> 2;               // 0..127
            int c4  = idx & 3;                // 0..3
            float4 v = *(const float4*)(xb + (size_t)row * Cn + k0 + c4 * 4);
            AsT[c4*4+0][row] = v.x;
            AsT[c4*4+1][row] = v.y;
            AsT[c4*4+2][row] = v.z;
            AsT[c4*4+3][row] = v.w;
        }
        // Load w tile 16x64
        {
            int row = tid >> 4, c4 = tid & 15;
            float4 v = *(const float4*)(w + (size_t)(k0 + row) * Dn + c4 * 4);
            *(float4*)(&Bs[row][c4 * 4]) = v;
        }
        __syncthreads();

        #pragma unroll
        for (int k = 0; k < 16; k++) {
            float a[8], bb[4];
            *(float4*)(a)     = *(const float4*)(&AsT[k][ty * 8]);
            *(float4*)(a + 4) = *(const float4*)(&AsT[k][ty * 8 + 4]);
            *(float4*)(bb)    = *(const float4*)(&Bs[k][tx * 4]);
            #pragma unroll
            for (int i = 0; i < 8; i++)
                #pragma unroll
                for (int j = 0; j < 4; j++)
                    acc[i][j] = fmaf(a[i], bb[j], acc[i][j]);
        }
        __syncthreads();
    }

    #pragma unroll
    for (int i = 0; i < 8; i++) {
        float4 v = make_float4(acc[i][0], acc[i][1], acc[i][2], acc[i][3]);
        *(float4*)(outp + (size_t)(ty * 8 + i) * Dn + tx * 4) = v;
    }
}

// ---------------------------------------------------------------------------
// Kernel 2: causal flash attention, fp32.
// Grid: (T/128, B*H). Block 256. Q tile 128 rows, key tiles of 64.
// Online softmax; P round-trips through smem for the PV GEMM.
// Output written straight into [B, T, H*D] layout (g_att).
// Dynamic smem: QsT[64][132] + PsT[64][132] + KsT[64][68] + Vs[64][68]
// ---------------------------------------------------------------------------
#define ATTN_SMEM_FLOATS (2*64*132 + 2*64*68)
#define ATTN_SMEM_BYTES  (ATTN_SMEM_FLOATS * 4)

__global__ __launch_bounds__(256, 2) void attn_kernel()
{
    extern __shared__ float sm[];
    float* QsT = sm;                         // [64 d][132]  (k-major Q, pre-scaled)
    float* PsT = sm + 64 * 132;              // [64 s][132]  (P transposed: col-major)
    float* KsT = sm + 2 * 64 * 132;          // [64 d][68]
    float* Vs  = sm + 2 * 64 * 132 + 64*68;  // [64 s][68]

    const int tid = threadIdx.x;
    const int qt  = blockIdx.x;      // 128-query tile
    const int bh  = blockIdx.y;
    const int b   = bh >> 4;
    const int h   = bh & 15;
    const int ty  = tid >> 4;        // rows ty*8..+7 (of 128)
    const int tx  = tid & 15;        // key cols / out cols tx*4..+3 (of 64)
    const float scale = 0.03125f;    // C^-0.5 = 1/32

    const float* qptr  = g_q + (size_t)bh * Tn * Dn + (size_t)qt * 128 * Dn;
    const float* kbase = g_k + (size_t)bh * Tn * Dn;
    const float* vbase = g_v + (size_t)bh * Tn * Dn;

    // Load Q tile (128x64), scaled, transposed to QsT[d][r]
    #pragma unroll
    for (int i = 0; i < 8; i++) {
        int idx = tid + i * 256;     // 0..2047 float4 slots (128 rows x 16)
        int row = idx >> 4;
        int c4  = idx & 15;
        float4 v = *(const float4*)(qptr + (size_t)row * Dn + c4 * 4);
        QsT[(c4*4+0)*132 + row] = v.x * scale;
        QsT[(c4*4+1)*132 + row] = v.y * scale;
        QsT[(c4*4+2)*132 + row] = v.z * scale;
        QsT[(c4*4+3)*132 + row] = v.w * scale;
    }

    float m[8], l[8], acc[8][4];
    #pragma unroll
    for (int i = 0; i < 8; i++) {
        m[i] = -1e30f; l[i] = 0.0f;
        #pragma unroll
        for (int j = 0; j < 4; j++) acc[i][j] = 0.0f;
    }

    const int jmax = 2 * qt + 1;     // inclusive last key tile (causal)
    for (int jt = 0; jt <= jmax; jt++) {
        __syncthreads();   // prior iter done with KsT/Vs/PsT; Q store visible after 2nd sync

        const float* kp = kbase + (size_t)jt * 64 * Dn;
        const float* vp = vbase + (size_t)jt * 64 * Dn;
        #pragma unroll
        for (int i = 0; i < 4; i++) {
            int idx = tid + i * 256;   // 0..1023 (64 rows x 16 f4)
            int row = idx >> 4;
            int c4  = idx & 15;
            float4 kv = *(const float4*)(kp + (size_t)row * Dn + c4 * 4);
            KsT[(c4*4+0)*68 + row] = kv.x;
            KsT[(c4*4+1)*68 + row] = kv.y;
            KsT[(c4*4+2)*68 + row] = kv.z;
            KsT[(c4*4+3)*68 + row] = kv.w;
            float4 vv = *(const float4*)(vp + (size_t)row * Dn + c4 * 4);
            *(float4*)(&Vs[row * 68 + c4 * 4]) = vv;
        }
        __syncthreads();

        // scores S = Qscaled @ K^T : s[8][4]
        float s[8][4] = {};
        #pragma unroll 16
        for (int k = 0; k < 64; k++) {
            float a[8], kk[4];
            *(float4*)(a)     = *(const float4*)(&QsT[k * 132 + ty * 8]);
            *(float4*)(a + 4) = *(const float4*)(&QsT[k * 132 + ty * 8 + 4]);
            *(float4*)(kk)    = *(const float4*)(&KsT[k * 68 + tx * 4]);
            #pragma unroll
            for (int i = 0; i < 8; i++)
                #pragma unroll
                for (int j = 0; j < 4; j++)
                    s[i][j] = fmaf(a[i], kk[j], s[i][j]);
        }

        // causal mask: only the last two tiles can cross the diagonal
        if (jt >= 2 * qt) {
            const int qrow0 = qt * 128 + ty * 8;
            const int kcol0 = jt * 64 + tx * 4;
            #pragma unroll
            for (int i = 0; i < 8; i++)
                #pragma unroll
                for (int j = 0; j < 4; j++)
                    if (kcol0 + j > qrow0 + i) s[i][j] = -1e30f;
        }

        // online softmax (row groups: 16 lanes sharing ty; xor<=8 stays in half-warp)
        #pragma unroll
        for (int i = 0; i < 8; i++) {
            float mt = s[i][0];
            mt = fmaxf(mt, s[i][1]); mt = fmaxf(mt, s[i][2]); mt = fmaxf(mt, s[i][3]);
            #pragma unroll
            for (int off = 8; off; off >>= 1)
                mt = fmaxf(mt, __shfl_xor_sync(0xffffffffu, mt, off));
            float mn = fmaxf(m[i], mt);
            float al = __expf(m[i] - mn);
            l[i] *= al;
            #pragma unroll
            for (int j = 0; j < 4; j++) acc[i][j] *= al;
            float rsum = 0.0f;
            #pragma unroll
            for (int j = 0; j < 4; j++) {
                float pp = __expf(s[i][j] - mn);
                s[i][j] = pp;
                rsum += pp;
            }
            #pragma unroll
            for (int off = 8; off; off >>= 1)
                rsum += __shfl_xor_sync(0xffffffffu, rsum, off);
            l[i] += rsum;
            m[i] = mn;
        }

        // write P transposed: PsT[keycol][qrow]
        #pragma unroll
        for (int i = 0; i < 8; i++)
            #pragma unroll
            for (int j = 0; j < 4; j++)
                PsT[(tx * 4 + j) * 132 + (ty * 8 + i)] = s[i][j];
        __syncthreads();

        // O += P @ V
        #pragma unroll 16
        for (int ss = 0; ss < 64; ss++) {
            float p[8], v[4];
            *(float4*)(p)     = *(const float4*)(&PsT[ss * 132 + ty * 8]);
            *(float4*)(p + 4) = *(const float4*)(&PsT[ss * 132 + ty * 8 + 4]);
            *(float4*)(v)     = *(const float4*)(&Vs[ss * 68 + tx * 4]);
            #pragma unroll
            for (int i = 0; i < 8; i++)
                #pragma unroll
                for (int j = 0; j < 4; j++)
                    acc[i][j] = fmaf(p[i], v[j], acc[i][j]);
        }
    }

    // normalize + write to [B, T, H*D]
    #pragma unroll
    for (int i = 0; i < 8; i++) {
        float inv = 1.0f / l[i];
        int t = qt * 128 + ty * 8 + i;
        float4 o = make_float4(acc[i][0]*inv, acc[i][1]*inv, acc[i][2]*inv, acc[i][3]*inv);
        *(float4*)(g_att + (size_t)b * Tn * Cn + (size_t)t * Cn + h * 64 + tx * 4) = o;
    }
}

// ---------------------------------------------------------------------------
// Kernel 3: output projection.  out[M=8192, N=1024] = g_att @ w_proj + bias
// Grid: (N/128, M/128). Block 256. Tile 128x128, BK=16, 8x8 per thread.
// ---------------------------------------------------------------------------
__global__ __launch_bounds__(256, 2) void proj_kernel(
    const float* __restrict__ w,
    const float* __restrict__ bias,
    float* __restrict__ out)
{
    __shared__ float AsT[16][132];
    __shared__ float Bs[16][128];

    const int tid = threadIdx.x;
    const int nb  = blockIdx.x;   // col tile
    const int mb  = blockIdx.y;   // row tile
    const int ty  = tid >> 4;
    const int tx  = tid & 15;

    const float* A = g_att + (size_t)mb * 128 * Cn;

    float acc[8][8] = {};

    for (int k0 = 0; k0 < Cn; k0 += 16) {
        #pragma unroll
        for (int i = 0; i < 2; i++) {
            int idx = tid + i * 256;   // 512 f4 slots: 128 rows x 4
            int row = idx >> 2;
            int c4  = idx & 3;
            float4 v = *(const float4*)(A + (size_t)row * Cn + k0 + c4 * 4);
            AsT[c4*4+0][row] = v.x;
            AsT[c4*4+1][row] = v.y;
            AsT[c4*4+2][row] = v.z;
            AsT[c4*4+3][row] = v.w;
        }
        #pragma unroll
        for (int i = 0; i < 2; i++) {
            int idx = tid + i * 256;   // 512 f4 slots: 16 rows x 32
            int row = idx >> 5;
            int c4  = idx & 31;
            float4 v = *(const float4*)(w + (size_t)(k0 + row) * Cn + nb * 128 + c4 * 4);
            *(float4*)(&Bs[row][c4 * 4]) = v;
        }
        __syncthreads();

        #pragma unroll
        for (int k = 0; k < 16; k++) {
            float a[8], bb[8];
            *(float4*)(a)      = *(const float4*)(&AsT[k][ty * 8]);
            *(float4*)(a + 4)  = *(const float4*)(&AsT[k][ty * 8 + 4]);
            *(float4*)(bb)     = *(const float4*)(&Bs[k][tx * 8]);
            *(float4*)(bb + 4) = *(const float4*)(&Bs[k][tx * 8 + 4]);
            #pragma unroll
            for (int i = 0; i < 8; i++)
                #pragma unroll
                for (int j = 0; j < 8; j++)
                    acc[i][j] = fmaf(a[i], bb[j], acc[i][j]);
        }
        __syncthreads();
    }

    #pragma unroll
    for (int i = 0; i < 8; i++) {
        int row = mb * 128 + ty * 8 + i;
        #pragma unroll
        for (int j4 = 0; j4 < 2; j4++) {
            int col = nb * 128 + tx * 8 + j4 * 4;
            float4 bv = *(const float4*)(bias + col);
            float4 o = make_float4(acc[i][j4*4+0] + bv.x,
                                   acc[i][j4*4+1] + bv.y,
                                   acc[i][j4*4+2] + bv.z,
                                   acc[i][j4*4+3] + bv.w);
            *(float4*)(out + (size_t)row * Cn + col) = o;
        }
    }
}

// ---------------------------------------------------------------------------
extern "C" void kernel_launch(void* const* d_in, const int* in_sizes, int n_in,
                              void* d_out, int out_size)
{
    const float* x      = (const float*)d_in[0];
    const float* wq     = (const float*)d_in[1];
    const float* wk     = (const float*)d_in[2];
    const float* wv     = (const float*)d_in[3];
    const float* w_proj = (const float*)d_in[4];
    const float* b_proj = (const float*)d_in[5];
    float* out = (float*)d_out;

    // QKV projections
    qkv_kernel<<<dim3(Tn/128, Bn*Hn, 3), 256>>>(x, wq, wk, wv);

    // Attention (needs >48KB dynamic smem)
    cudaFuncSetAttribute(attn_kernel,
                         cudaFuncAttributeMaxDynamicSharedMemorySize,
                         ATTN_SMEM_BYTES);
    attn_kernel<<<dim3(Tn/128, Bn*Hn), 256, ATTN_SMEM_BYTES>>>();

    // Output projection + bias
    proj_kernel<<<dim3(Cn/128, (Bn*Tn)/128), 256>>>(w_proj, b_proj, out);
}

// round 4
// speedup vs baseline: 1.4612x; 1.4612x over previous
#include <cuda_runtime.h>
#include <cuda_bf16.h>
#include <cstdint>

// Problem constants
#define Bn 4
#define Tn 2048
#define Cn 1024
#define Hn 16
#define Dn 64
#define Mrows (Bn*Tn)   // 8192

// ---------------------------------------------------------------------------
// Scratch (allocation-free rule: __device__ globals). 16B-aligned for
// float4 / cp.async.cg 16-byte accesses.
// ---------------------------------------------------------------------------
__device__ __align__(16) float g_q[Bn*Hn*Tn*Dn];    // [B*H, T, D] fp32
__device__ __align__(16) float g_k[Bn*Hn*Tn*Dn];
__device__ __align__(16) float g_v[Bn*Hn*Tn*Dn];
__device__ __align__(16) float g_att[Bn*Tn*Cn];     // [B, T, H*D] fp32

__device__ __align__(16) __nv_bfloat16 g_xhi[Mrows*Cn];
__device__ __align__(16) __nv_bfloat16 g_xlo[Mrows*Cn];
__device__ __align__(16) __nv_bfloat16 g_wt_hi[3*Cn*Cn];   // [3][N][K]
__device__ __align__(16) __nv_bfloat16 g_wt_lo[3*Cn*Cn];
__device__ __align__(16) __nv_bfloat16 g_wpt_hi[Cn*Cn];    // [N][K]
__device__ __align__(16) __nv_bfloat16 g_wpt_lo[Cn*Cn];
__device__ __align__(16) __nv_bfloat16 g_atthi[Mrows*Cn];
__device__ __align__(16) __nv_bfloat16 g_attlo[Mrows*Cn];

// ---------------------------------------------------------------------------
// PTX helpers (sm_100-portable: mma.sync / ldmatrix / cp.async)
// ---------------------------------------------------------------------------
__device__ __forceinline__ uint32_t smem_to_u32(const void* p) {
    uint32_t a;
    asm("{ .reg .u64 t; cvta.to.shared.u64 t, %1; cvt.u32.u64 %0, t; }"
        : "=r"(a) : "l"(p));
    return a;
}
__device__ __forceinline__ void cp16(uint32_t dst, const void* src) {
    asm volatile("cp.async.cg.shared.global [%0], [%1], 16;"
                 :: "r"(dst), "l"(src) : "memory");
}
__device__ __forceinline__ void cp_commit() {
    asm volatile("cp.async.commit_group;" ::: "memory");
}
__device__ __forceinline__ void ldsm4(uint32_t (&r)[4], uint32_t addr) {
    asm volatile("ldmatrix.sync.aligned.m8n8.x4.shared.b16 {%0,%1,%2,%3}, [%4];"
                 : "=r"(r[0]), "=r"(r[1]), "=r"(r[2]), "=r"(r[3]) : "r"(addr));
}
__device__ __forceinline__ void mma16816(float (&c)[4], const uint32_t (&a)[4],
                                         uint32_t b0, uint32_t b1) {
    asm volatile(
        "mma.sync.aligned.m16n8k16.row.col.f32.bf16.bf16.f32 "
        "{%0,%1,%2,%3}, {%4,%5,%6,%7}, {%8,%9}, {%0,%1,%2,%3};"
        : "+f"(c[0]), "+f"(c[1]), "+f"(c[2]), "+f"(c[3])
        : "r"(a[0]), "r"(a[1]), "r"(a[2]), "r"(a[3]), "r"(b0), "r"(b1));
}

// ---------------------------------------------------------------------------
// Split fp32 -> (hi, lo) bf16. which=0: x (param) -> g_xhi/lo
//                              which=1: g_att     -> g_atthi/lo
// ---------------------------------------------------------------------------
__global__ void split_kernel(const float* __restrict__ xsrc, int which)
{
    int i = blockIdx.x * blockDim.x + threadIdx.x;
    if (i >= Mrows * Cn / 4) return;
    const float4* s = which ? (const float4*)g_att : (const float4*)xsrc;
    __nv_bfloat16* hi = which ? g_atthi : g_xhi;
    __nv_bfloat16* lo = which ? g_attlo : g_xlo;
    float4 v = s[i];
    float a[4] = {v.x, v.y, v.z, v.w};
    __nv_bfloat16 h[4], l[4];
    #pragma unroll
    for (int j = 0; j < 4; j++) {
        h[j] = __float2bfloat16(a[j]);
        l[j] = __float2bfloat16(a[j] - __bfloat162float(h[j]));
    }
    *(__nv_bfloat162*)(hi + (size_t)i*4)     = __nv_bfloat162(h[0], h[1]);
    *(__nv_bfloat162*)(hi + (size_t)i*4 + 2) = __nv_bfloat162(h[2], h[3]);
    *(__nv_bfloat162*)(lo + (size_t)i*4)     = __nv_bfloat162(l[0], l[1]);
    *(__nv_bfloat162*)(lo + (size_t)i*4 + 2) = __nv_bfloat162(l[2], l[3]);
}

// ---------------------------------------------------------------------------
// Transpose+split: in [Z][R][Cols] fp32 -> dst [Z][Cols][R] (hi,lo) bf16
// sel 0..2 -> g_wt_* + sel*Cn*Cn ; sel 3 -> g_wpt_*
// Grid (Cols/32, R/32, Z), block (32,8)
// ---------------------------------------------------------------------------
__global__ void transpose_split_k(const float* __restrict__ in,
                                  int R, int Cols, int sel)
{
    __shared__ float t[32][33];
    __nv_bfloat16* ohi = (sel < 3) ? g_wt_hi + (size_t)sel*Cn*Cn : g_wpt_hi;
    __nv_bfloat16* olo = (sel < 3) ? g_wt_lo + (size_t)sel*Cn*Cn : g_wpt_lo;
    const int z = blockIdx.z;
    const float* src = in + (size_t)z * R * Cols;
    __nv_bfloat16* dhi = ohi + (size_t)z * R * Cols;
    __nv_bfloat16* dlo = olo + (size_t)z * R * Cols;
    const int c0 = blockIdx.x * 32, r0 = blockIdx.y * 32;
    const int tx = threadIdx.x, ty = threadIdx.y;
    #pragma unroll
    for (int j = 0; j < 4; j++)
        t[ty + 8*j][tx] = src[(size_t)(r0 + ty + 8*j) * Cols + c0 + tx];
    __syncthreads();
    #pragma unroll
    for (int j = 0; j < 4; j++) {
        float a = t[tx][ty + 8*j];
        __nv_bfloat16 h = __float2bfloat16(a);
        size_t o = (size_t)(c0 + ty + 8*j) * R + r0 + tx;
        dhi[o] = h;
        dlo[o] = __float2bfloat16(a - __bfloat162float(h));
    }
}

// ---------------------------------------------------------------------------
// bf16x3 HMMA GEMM: C[8192,1024] = A * B^T   (B stored [N][K])
// Tile 128x128, BK=32, 8 warps (2x4), warp tile 64x32, double-buffered cp.async.
// mode 0: QKV (z = 0/1/2, scatter into g_q/g_k/g_v [B*H][T][D])
// mode 1: proj (+bias -> outp)
// ---------------------------------------------------------------------------
#define KPITCH 40                 // bf16 per smem row (32 data + 8 pad)
#define ROWB   (KPITCH*2)         // 80 bytes
#define TILEB  (128*ROWB)         // 10240 bytes per tile
#define STAGEB (4*TILEB)          // Ah, Al, Bh, Bl
#define GSMEM  (2*STAGEB)         // 81920 bytes
#define NCHUNK (Cn/32)            // 32

__device__ __forceinline__ void load_chunk(uint32_t sbase,
    const __nv_bfloat16* __restrict__ Ah, const __nv_bfloat16* __restrict__ Al,
    const __nv_bfloat16* __restrict__ Bh, const __nv_bfloat16* __restrict__ Bl,
    int k0, int tid)
{
    const __nv_bfloat16* gsrc[4] = {Ah, Al, Bh, Bl};
    #pragma unroll
    for (int a = 0; a < 4; a++) {
        #pragma unroll
        for (int j = 0; j < 2; j++) {
            int o = tid + j * 256;           // 0..511
            int row = o >> 2, ch = o & 3;
            cp16(sbase + a * TILEB + row * ROWB + ch * 16,
                 gsrc[a] + (size_t)row * Cn + k0 + ch * 8);
        }
    }
}

__global__ __launch_bounds__(256) void gemm_hmma(
    const float* __restrict__ bias, float* __restrict__ outp, int mode)
{
    extern __shared__ __align__(128) char smem[];
    const uint32_t smem_base = smem_to_u32(smem);
    const int tid = threadIdx.x;
    const int lane = tid & 31, wid = tid >> 5;
    const int wm = wid >> 2, wn = wid & 3;   // 2 x 4 warp grid
    const int nb = blockIdx.x, mt = blockIdx.y, z = blockIdx.z;

    const __nv_bfloat16* Agh = (mode == 0 ? g_xhi : g_atthi) + (size_t)mt * 128 * Cn;
    const __nv_bfloat16* Agl = (mode == 0 ? g_xlo : g_attlo) + (size_t)mt * 128 * Cn;
    const __nv_bfloat16* Bgh = (mode == 0 ? g_wt_hi + (size_t)z * Cn * Cn : g_wpt_hi)
                               + (size_t)nb * 128 * Cn;
    const __nv_bfloat16* Bgl = (mode == 0 ? g_wt_lo + (size_t)z * Cn * Cn : g_wpt_lo)
                               + (size_t)nb * 128 * Cn;

    float acc[4][4][4] = {};

    // ldmatrix lane addressing (constant per thread)
    const uint32_t a_row  = (lane & 15);            // row within 16
    const uint32_t a_kb   = (lane >> 4) << 4;       // 0 or 16 bytes (k8 half)
    const uint32_t b_noff = ((lane >> 4) << 3) + (lane & 7);  // 0..15
    const uint32_t b_kb   = ((lane >> 3) & 1) << 4; // 0 or 16 bytes

    load_chunk(smem_base, Agh, Agl, Bgh, Bgl, 0, tid);
    cp_commit();

    for (int i = 0; i < NCHUNK; i++) {
        const int buf = i & 1;
        if (i + 1 < NCHUNK) {
            load_chunk(smem_base + (buf ^ 1) * STAGEB, Agh, Agl, Bgh, Bgl,
                       (i + 1) * 32, tid);
            cp_commit();
            asm volatile("cp.async.wait_group 1;" ::: "memory");
        } else {
            asm volatile("cp.async.wait_group 0;" ::: "memory");
        }
        __syncthreads();

        const uint32_t sb = smem_base + buf * STAGEB;
        #pragma unroll
        for (int ks = 0; ks < 2; ks++) {
            // k16 step = 16 bf16 = 32 bytes
            uint32_t bh[2][4], bl[2][4];
            #pragma unroll
            for (int p = 0; p < 2; p++) {
                uint32_t n = wn * 32 + p * 16 + b_noff;
                uint32_t off = n * ROWB + ks * 32 + b_kb;
                ldsm4(bh[p], sb + 2 * TILEB + off);
                ldsm4(bl[p], sb + 3 * TILEB + off);
            }
            #pragma unroll
            for (int mi = 0; mi < 4; mi++) {
                uint32_t r = wm * 64 + mi * 16 + a_row;
                uint32_t off = r * ROWB + ks * 32 + a_kb;
                uint32_t ah[4], al[4];
                ldsm4(ah, sb + off);
                ldsm4(al, sb + TILEB + off);
                #pragma unroll
                for (int j = 0; j < 4; j++) {
                    uint32_t b0h = bh[j >> 1][(j & 1) * 2], b1h = bh[j >> 1][(j & 1) * 2 + 1];
                    uint32_t b0l = bl[j >> 1][(j & 1) * 2], b1l = bl[j >> 1][(j & 1) * 2 + 1];
                    mma16816(acc[mi][j], ah, b0h, b1h);
                    mma16816(acc[mi][j], ah, b0l, b1l);
                    mma16816(acc[mi][j], al, b0h, b1h);
                }
            }
        }
        __syncthreads();
    }

    // Epilogue
    const int lr = lane >> 2;           // 0..7
    const int lc = (lane & 3) * 2;      // 0,2,4,6
    #pragma unroll
    for (int mi = 0; mi < 4; mi++) {
        #pragma unroll
        for (int j = 0; j < 4; j++) {
            int row = mt * 128 + wm * 64 + mi * 16 + lr;
            int col = nb * 128 + wn * 32 + j * 8 + lc;
            if (mode == 1) {
                float2 bv = *(const float2*)(bias + col);
                float2 o0 = make_float2(acc[mi][j][0] + bv.x, acc[mi][j][1] + bv.y);
                float2 o1 = make_float2(acc[mi][j][2] + bv.x, acc[mi][j][3] + bv.y);
                *(float2*)(outp + (size_t)row * Cn + col) = o0;
                *(float2*)(outp + (size_t)(row + 8) * Cn + col) = o1;
            } else {
                int b = row >> 11, t = row & 2047;
                int h = col >> 6, d = col & 63;
                float* base = (z == 0 ? g_q : (z == 1 ? g_k : g_v));
                float* dst = base + ((size_t)((b << 4) + h) * Tn + t) * Dn + d;
                *(float2*)dst = make_float2(acc[mi][j][0], acc[mi][j][1]);
                *(float2*)(dst + 8 * Dn) = make_float2(acc[mi][j][2], acc[mi][j][3]);
            }
        }
    }
}

// ---------------------------------------------------------------------------
// Causal flash attention, fp32 SIMT (unchanged from R1)
// ---------------------------------------------------------------------------
#define ATTN_SMEM_FLOATS (2*64*132 + 2*64*68)
#define ATTN_SMEM_BYTES  (ATTN_SMEM_FLOATS * 4)

__global__ __launch_bounds__(256, 2) void attn_kernel()
{
    extern __shared__ float sm[];
    float* QsT = sm;
    float* PsT = sm + 64 * 132;
    float* KsT = sm + 2 * 64 * 132;
    float* Vs  = sm + 2 * 64 * 132 + 64*68;

    const int tid = threadIdx.x;
    const int qt  = blockIdx.x;
    const int bh  = blockIdx.y;
    const int b   = bh >> 4;
    const int h   = bh & 15;
    const int ty  = tid >> 4;
    const int tx  = tid & 15;
    const float scale = 0.03125f;

    const float* qptr  = g_q + (size_t)bh * Tn * Dn + (size_t)qt * 128 * Dn;
    const float* kbase = g_k + (size_t)bh * Tn * Dn;
    const float* vbase = g_v + (size_t)bh * Tn * Dn;

    #pragma unroll
    for (int i = 0; i < 8; i++) {
        int idx = tid + i * 256;
        int row = idx >> 4;
        int c4  = idx & 15;
        float4 v = *(const float4*)(qptr + (size_t)row * Dn + c4 * 4);
        QsT[(c4*4+0)*132 + row] = v.x * scale;
        QsT[(c4*4+1)*132 + row] = v.y * scale;
        QsT[(c4*4+2)*132 + row] = v.z * scale;
        QsT[(c4*4+3)*132 + row] = v.w * scale;
    }

    float m[8], l[8], acc[8][4];
    #pragma unroll
    for (int i = 0; i < 8; i++) {
        m[i] = -1e30f; l[i] = 0.0f;
        #pragma unroll
        for (int j = 0; j < 4; j++) acc[i][j] = 0.0f;
    }

    const int jmax = 2 * qt + 1;
    for (int jt = 0; jt <= jmax; jt++) {
        __syncthreads();

        const float* kp = kbase + (size_t)jt * 64 * Dn;
        const float* vp = vbase + (size_t)jt * 64 * Dn;
        #pragma unroll
        for (int i = 0; i < 4; i++) {
            int idx = tid + i * 256;
            int row = idx >> 4;
            int c4  = idx & 15;
            float4 kv = *(const float4*)(kp + (size_t)row * Dn + c4 * 4);
            KsT[(c4*4+0)*68 + row] = kv.x;
            KsT[(c4*4+1)*68 + row] = kv.y;
            KsT[(c4*4+2)*68 + row] = kv.z;
            KsT[(c4*4+3)*68 + row] = kv.w;
            float4 vv = *(const float4*)(vp + (size_t)row * Dn + c4 * 4);
            *(float4*)(&Vs[row * 68 + c4 * 4]) = vv;
        }
        __syncthreads();

        float s[8][4] = {};
        #pragma unroll 16
        for (int k = 0; k < 64; k++) {
            float a[8], kk[4];
            *(float4*)(a)     = *(const float4*)(&QsT[k * 132 + ty * 8]);
            *(float4*)(a + 4) = *(const float4*)(&QsT[k * 132 + ty * 8 + 4]);
            *(float4*)(kk)    = *(const float4*)(&KsT[k * 68 + tx * 4]);
            #pragma unroll
            for (int i = 0; i < 8; i++)
                #pragma unroll
                for (int j = 0; j < 4; j++)
                    s[i][j] = fmaf(a[i], kk[j], s[i][j]);
        }

        if (jt >= 2 * qt) {
            const int qrow0 = qt * 128 + ty * 8;
            const int kcol0 = jt * 64 + tx * 4;
            #pragma unroll
            for (int i = 0; i < 8; i++)
                #pragma unroll
                for (int j = 0; j < 4; j++)
                    if (kcol0 + j > qrow0 + i) s[i][j] = -1e30f;
        }

        #pragma unroll
        for (int i = 0; i < 8; i++) {
            float mt = s[i][0];
            mt = fmaxf(mt, s[i][1]); mt = fmaxf(mt, s[i][2]); mt = fmaxf(mt, s[i][3]);
            #pragma unroll
            for (int off = 8; off; off >>= 1)
                mt = fmaxf(mt, __shfl_xor_sync(0xffffffffu, mt, off));
            float mn = fmaxf(m[i], mt);
            float al = __expf(m[i] - mn);
            l[i] *= al;
            #pragma unroll
            for (int j = 0; j < 4; j++) acc[i][j] *= al;
            float rsum = 0.0f;
            #pragma unroll
            for (int j = 0; j < 4; j++) {
                float pp = __expf(s[i][j] - mn);
                s[i][j] = pp;
                rsum += pp;
            }
            #pragma unroll
            for (int off = 8; off; off >>= 1)
                rsum += __shfl_xor_sync(0xffffffffu, rsum, off);
            l[i] += rsum;
            m[i] = mn;
        }

        #pragma unroll
        for (int i = 0; i < 8; i++)
            #pragma unroll
            for (int j = 0; j < 4; j++)
                PsT[(tx * 4 + j) * 132 + (ty * 8 + i)] = s[i][j];
        __syncthreads();

        #pragma unroll 16
        for (int ss = 0; ss < 64; ss++) {
            float p[8], v[4];
            *(float4*)(p)     = *(const float4*)(&PsT[ss * 132 + ty * 8]);
            *(float4*)(p + 4) = *(const float4*)(&PsT[ss * 132 + ty * 8 + 4]);
            *(float4*)(v)     = *(const float4*)(&Vs[ss * 68 + tx * 4]);
            #pragma unroll
            for (int i = 0; i < 8; i++)
                #pragma unroll
                for (int j = 0; j < 4; j++)
                    acc[i][j] = fmaf(p[i], v[j], acc[i][j]);
        }
    }

    #pragma unroll
    for (int i = 0; i < 8; i++) {
        float inv = 1.0f / l[i];
        int t = qt * 128 + ty * 8 + i;
        float4 o = make_float4(acc[i][0]*inv, acc[i][1]*inv, acc[i][2]*inv, acc[i][3]*inv);
        *(float4*)(g_att + (size_t)b * Tn * Cn + (size_t)t * Cn + h * 64 + tx * 4) = o;
    }
}

// ---------------------------------------------------------------------------
extern "C" void kernel_launch(void* const* d_in, const int* in_sizes, int n_in,
                              void* d_out, int out_size)
{
    const float* x      = (const float*)d_in[0];
    const float* wq     = (const float*)d_in[1];
    const float* wk     = (const float*)d_in[2];
    const float* wv     = (const float*)d_in[3];
    const float* w_proj = (const float*)d_in[4];
    const float* b_proj = (const float*)d_in[5];
    float* out = (float*)d_out;

    cudaFuncSetAttribute(attn_kernel,
                         cudaFuncAttributeMaxDynamicSharedMemorySize,
                         ATTN_SMEM_BYTES);
    cudaFuncSetAttribute(gemm_hmma,
                         cudaFuncAttributeMaxDynamicSharedMemorySize,
                         GSMEM);

    // 1) split x -> bf16 hi/lo
    int n4 = Mrows * Cn / 4;
    split_kernel<<<(n4 + 255) / 256, 256>>>(x, 0);

    // 2) transpose + split weights
    transpose_split_k<<<dim3(Dn/32, Cn/32, Hn), dim3(32,8)>>>(wq, Cn, Dn, 0);
    transpose_split_k<<<dim3(Dn/32, Cn/32, Hn), dim3(32,8)>>>(wk, Cn, Dn, 1);
    transpose_split_k<<<dim3(Dn/32, Cn/32, Hn), dim3(32,8)>>>(wv, Cn, Dn, 2);
    transpose_split_k<<<dim3(Cn/32, Cn/32, 1),  dim3(32,8)>>>(w_proj, Cn, Cn, 3);

    // 3) QKV GEMMs (tensor cores, bf16x3)
    gemm_hmma<<<dim3(Cn/128, Mrows/128, 3), 256, GSMEM>>>(nullptr, nullptr, 0);

    // 4) attention (fp32 SIMT)
    attn_kernel<<<dim3(Tn/128, Bn*Hn), 256, ATTN_SMEM_BYTES>>>();

    // 5) split attention output -> bf16 hi/lo
    split_kernel<<<(n4 + 255) / 256, 256>>>(nullptr, 1);

    // 6) output projection (tensor cores, bf16x3, +bias)
    gemm_hmma<<<dim3(Cn/128, Mrows/128, 1), 256, GSMEM>>>(b_proj, out, 1);
}

// round 5
// speedup vs baseline: 2.5358x; 1.7354x over previous
#include <cuda_runtime.h>
#include <cuda_bf16.h>
#include <cstdint>

// Problem constants
#define Bn 4
#define Tn 2048
#define Cn 1024
#define Hn 16
#define Dn 64
#define Mrows (Bn*Tn)   // 8192

// ---------------------------------------------------------------------------
// Scratch (allocation-free rule: __device__ globals), 16B-aligned
// ---------------------------------------------------------------------------
__device__ __align__(16) float g_v[Bn*Hn*Tn*Dn];    // [B*H][T][D] fp32
__device__ __align__(16) float g_att[Bn*Tn*Cn];     // [B][T][H*D] fp32

__device__ __align__(16) __nv_bfloat16 g_qhi[Bn*Hn*Tn*Dn];  // [B*H][T][D], pre-scaled
__device__ __align__(16) __nv_bfloat16 g_qlo[Bn*Hn*Tn*Dn];
__device__ __align__(16) __nv_bfloat16 g_khi[Bn*Hn*Tn*Dn];
__device__ __align__(16) __nv_bfloat16 g_klo[Bn*Hn*Tn*Dn];
__device__ __align__(16) __nv_bfloat16 g_vthi[Bn*Hn*Dn*Tn]; // [B*H][D][T] (V^T)
__device__ __align__(16) __nv_bfloat16 g_vtlo[Bn*Hn*Dn*Tn];

__device__ __align__(16) __nv_bfloat16 g_xhi[Mrows*Cn];
__device__ __align__(16) __nv_bfloat16 g_xlo[Mrows*Cn];
__device__ __align__(16) __nv_bfloat16 g_wt_hi[3*Cn*Cn];   // [3][N][K]
__device__ __align__(16) __nv_bfloat16 g_wt_lo[3*Cn*Cn];
__device__ __align__(16) __nv_bfloat16 g_wpt_hi[Cn*Cn];    // [N][K]
__device__ __align__(16) __nv_bfloat16 g_wpt_lo[Cn*Cn];
__device__ __align__(16) __nv_bfloat16 g_atthi[Mrows*Cn];
__device__ __align__(16) __nv_bfloat16 g_attlo[Mrows*Cn];

// ---------------------------------------------------------------------------
// PTX helpers (sm_100-portable)
// ---------------------------------------------------------------------------
__device__ __forceinline__ uint32_t smem_to_u32(const void* p) {
    uint32_t a;
    asm("{ .reg .u64 t; cvta.to.shared.u64 t, %1; cvt.u32.u64 %0, t; }"
        : "=r"(a) : "l"(p));
    return a;
}
__device__ __forceinline__ void cp16(uint32_t dst, const void* src) {
    asm volatile("cp.async.cg.shared.global [%0], [%1], 16;"
                 :: "r"(dst), "l"(src) : "memory");
}
__device__ __forceinline__ void cp_commit() {
    asm volatile("cp.async.commit_group;" ::: "memory");
}
__device__ __forceinline__ void ldsm4(uint32_t (&r)[4], uint32_t addr) {
    asm volatile("ldmatrix.sync.aligned.m8n8.x4.shared.b16 {%0,%1,%2,%3}, [%4];"
                 : "=r"(r[0]), "=r"(r[1]), "=r"(r[2]), "=r"(r[3]) : "r"(addr));
}
__device__ __forceinline__ void mma16816(float (&c)[4], const uint32_t (&a)[4],
                                         uint32_t b0, uint32_t b1) {
    asm volatile(
        "mma.sync.aligned.m16n8k16.row.col.f32.bf16.bf16.f32 "
        "{%0,%1,%2,%3}, {%4,%5,%6,%7}, {%8,%9}, {%0,%1,%2,%3};"
        : "+f"(c[0]), "+f"(c[1]), "+f"(c[2]), "+f"(c[3])
        : "r"(a[0]), "r"(a[1]), "r"(a[2]), "r"(a[3]), "r"(b0), "r"(b1));
}

// Fast exp on the FMA/ALU pipes (no MUFU). rel err ~3e-6. Handles -1e30 -> ~0.
__device__ __forceinline__ float fexp(float x) {
    float y = x * 1.4426950408889634f;
    y = fmaxf(y, -126.0f);
    float r = y + 12582912.0f;           // round-to-nearest-int magic
    float n = r - 12582912.0f;
    float f = y - n;                     // [-0.5, 0.5]
    int   e = __float_as_int(r);         // low bits hold n (two's complement)
    float u = f * 0.6931471805599453f;   // f*ln2
    float p = 8.3333333e-3f;             // 1/120
    p = fmaf(p, u, 4.1666667e-2f);
    p = fmaf(p, u, 1.6666667e-1f);
    p = fmaf(p, u, 5.0e-1f);
    p = fmaf(p, u, 1.0f);
    p = fmaf(p, u, 1.0f);
    int sc = (e - 0x4B400000 + 127) << 23;
    return __int_as_float(sc) * p;
}

__device__ __forceinline__ void split_pack(float a, float b,
                                           uint32_t& hi, uint32_t& lo) {
    __nv_bfloat16 ha = __float2bfloat16(a);
    __nv_bfloat16 hb = __float2bfloat16(b);
    __nv_bfloat16 la = __float2bfloat16(a - __bfloat162float(ha));
    __nv_bfloat16 lb = __float2bfloat16(b - __bfloat162float(hb));
    __nv_bfloat162 H(ha, hb), L(la, lb);
    hi = *reinterpret_cast<uint32_t*>(&H);
    lo = *reinterpret_cast<uint32_t*>(&L);
}

// ---------------------------------------------------------------------------
// Split fp32 -> (hi, lo) bf16. which=0: x -> g_xhi/lo ; which=1: g_att -> g_atthi/lo
// ---------------------------------------------------------------------------
__global__ void split_kernel(const float* __restrict__ xsrc, int which)
{
    int i = blockIdx.x * blockDim.x + threadIdx.x;
    if (i >= Mrows * Cn / 4) return;
    const float4* s = which ? (const float4*)g_att : (const float4*)xsrc;
    __nv_bfloat16* hi = which ? g_atthi : g_xhi;
    __nv_bfloat16* lo = which ? g_attlo : g_xlo;
    float4 v = s[i];
    float a[4] = {v.x, v.y, v.z, v.w};
    __nv_bfloat16 h[4], l[4];
    #pragma unroll
    for (int j = 0; j < 4; j++) {
        h[j] = __float2bfloat16(a[j]);
        l[j] = __float2bfloat16(a[j] - __bfloat162float(h[j]));
    }
    *(__nv_bfloat162*)(hi + (size_t)i*4)     = __nv_bfloat162(h[0], h[1]);
    *(__nv_bfloat162*)(hi + (size_t)i*4 + 2) = __nv_bfloat162(h[2], h[3]);
    *(__nv_bfloat162*)(lo + (size_t)i*4)     = __nv_bfloat162(l[0], l[1]);
    *(__nv_bfloat162*)(lo + (size_t)i*4 + 2) = __nv_bfloat162(l[2], l[3]);
}

// ---------------------------------------------------------------------------
// Transpose+split weights: in [Z][R][Cols] fp32 -> [Z][Cols][R] (hi,lo) bf16
// ---------------------------------------------------------------------------
__global__ void transpose_split_k(const float* __restrict__ in,
                                  int R, int Cols, int sel)
{
    __shared__ float t[32][33];
    __nv_bfloat16* ohi = (sel < 3) ? g_wt_hi + (size_t)sel*Cn*Cn : g_wpt_hi;
    __nv_bfloat16* olo = (sel < 3) ? g_wt_lo + (size_t)sel*Cn*Cn : g_wpt_lo;
    const int z = blockIdx.z;
    const float* src = in + (size_t)z * R * Cols;
    __nv_bfloat16* dhi = ohi + (size_t)z * R * Cols;
    __nv_bfloat16* dlo = olo + (size_t)z * R * Cols;
    const int c0 = blockIdx.x * 32, r0 = blockIdx.y * 32;
    const int tx = threadIdx.x, ty = threadIdx.y;
    #pragma unroll
    for (int j = 0; j < 4; j++)
        t[ty + 8*j][tx] = src[(size_t)(r0 + ty + 8*j) * Cols + c0 + tx];
    __syncthreads();
    #pragma unroll
    for (int j = 0; j < 4; j++) {
        float a = t[tx][ty + 8*j];
        __nv_bfloat16 h = __float2bfloat16(a);
        size_t o = (size_t)(c0 + ty + 8*j) * R + r0 + tx;
        dhi[o] = h;
        dlo[o] = __float2bfloat16(a - __bfloat162float(h));
    }
}

// ---------------------------------------------------------------------------
// V transpose+split: g_v [BH][T][D] fp32 -> g_vthi/lo [BH][D][T] bf16
// Grid (Tn/32, Dn/32, BH), block (32,8)
// ---------------------------------------------------------------------------
__global__ void v_transpose_split()
{
    __shared__ float t[32][33];
    const int z = blockIdx.z;
    const int t0 = blockIdx.x * 32, d0 = blockIdx.y * 32;
    const float* src = g_v + (size_t)z * Tn * Dn;
    __nv_bfloat16* dhi = g_vthi + (size_t)z * Dn * Tn;
    __nv_bfloat16* dlo = g_vtlo + (size_t)z * Dn * Tn;
    const int tx = threadIdx.x, ty = threadIdx.y;
    #pragma unroll
    for (int j = 0; j < 4; j++)
        t[ty + 8*j][tx] = src[(size_t)(t0 + ty + 8*j) * Dn + d0 + tx];
    __syncthreads();
    #pragma unroll
    for (int j = 0; j < 4; j++) {
        float a = t[tx][ty + 8*j];        // token t0+tx, d d0+ty+8j
        __nv_bfloat16 h = __float2bfloat16(a);
        size_t o = (size_t)(d0 + ty + 8*j) * Tn + t0 + tx;
        dhi[o] = h;
        dlo[o] = __float2bfloat16(a - __bfloat162float(h));
    }
}

// ---------------------------------------------------------------------------
// bf16x3 HMMA GEMM (as R4). mode 0: QKV — z=0 writes scaled q hi/lo bf16,
// z=1 writes k hi/lo bf16, z=2 writes fp32 g_v. mode 1: proj (+bias -> outp).
// ---------------------------------------------------------------------------
#define KPITCH 40
#define ROWB   (KPITCH*2)         // 80 B
#define TILEB  (128*ROWB)
#define STAGEB (4*TILEB)
#define GSMEM  (2*STAGEB)
#define NCHUNK (Cn/32)

__device__ __forceinline__ void load_chunk(uint32_t sbase,
    const __nv_bfloat16* __restrict__ Ah, const __nv_bfloat16* __restrict__ Al,
    const __nv_bfloat16* __restrict__ Bh, const __nv_bfloat16* __restrict__ Bl,
    int k0, int tid)
{
    const __nv_bfloat16* gsrc[4] = {Ah, Al, Bh, Bl};
    #pragma unroll
    for (int a = 0; a < 4; a++) {
        #pragma unroll
        for (int j = 0; j < 2; j++) {
            int o = tid + j * 256;
            int row = o >> 2, ch = o & 3;
            cp16(sbase + a * TILEB + row * ROWB + ch * 16,
                 gsrc[a] + (size_t)row * Cn + k0 + ch * 8);
        }
    }
}

__global__ __launch_bounds__(256) void gemm_hmma(
    const float* __restrict__ bias, float* __restrict__ outp, int mode)
{
    extern __shared__ __align__(128) char smem[];
    const uint32_t smem_base = smem_to_u32(smem);
    const int tid = threadIdx.x;
    const int lane = tid & 31, wid = tid >> 5;
    const int wm = wid >> 2, wn = wid & 3;
    const int nb = blockIdx.x, mt = blockIdx.y, z = blockIdx.z;

    const __nv_bfloat16* Agh = (mode == 0 ? g_xhi : g_atthi) + (size_t)mt * 128 * Cn;
    const __nv_bfloat16* Agl = (mode == 0 ? g_xlo : g_attlo) + (size_t)mt * 128 * Cn;
    const __nv_bfloat16* Bgh = (mode == 0 ? g_wt_hi + (size_t)z * Cn * Cn : g_wpt_hi)
                               + (size_t)nb * 128 * Cn;
    const __nv_bfloat16* Bgl = (mode == 0 ? g_wt_lo + (size_t)z * Cn * Cn : g_wpt_lo)
                               + (size_t)nb * 128 * Cn;

    float acc[4][4][4] = {};

    const uint32_t a_row  = (lane & 15);
    const uint32_t a_kb   = (lane >> 4) << 4;
    const uint32_t b_noff = ((lane >> 4) << 3) + (lane & 7);
    const uint32_t b_kb   = ((lane >> 3) & 1) << 4;

    load_chunk(smem_base, Agh, Agl, Bgh, Bgl, 0, tid);
    cp_commit();

    for (int i = 0; i < NCHUNK; i++) {
        const int buf = i & 1;
        if (i + 1 < NCHUNK) {
            load_chunk(smem_base + (buf ^ 1) * STAGEB, Agh, Agl, Bgh, Bgl,
                       (i + 1) * 32, tid);
            cp_commit();
            asm volatile("cp.async.wait_group 1;" ::: "memory");
        } else {
            asm volatile("cp.async.wait_group 0;" ::: "memory");
        }
        __syncthreads();

        const uint32_t sb = smem_base + buf * STAGEB;
        #pragma unroll
        for (int ks = 0; ks < 2; ks++) {
            uint32_t bh[2][4], bl[2][4];
            #pragma unroll
            for (int p = 0; p < 2; p++) {
                uint32_t n = wn * 32 + p * 16 + b_noff;
                uint32_t off = n * ROWB + ks * 32 + b_kb;
                ldsm4(bh[p], sb + 2 * TILEB + off);
                ldsm4(bl[p], sb + 3 * TILEB + off);
            }
            #pragma unroll
            for (int mi = 0; mi < 4; mi++) {
                uint32_t r = wm * 64 + mi * 16 + a_row;
                uint32_t off = r * ROWB + ks * 32 + a_kb;
                uint32_t ah[4], al[4];
                ldsm4(ah, sb + off);
                ldsm4(al, sb + TILEB + off);
                #pragma unroll
                for (int j = 0; j < 4; j++) {
                    uint32_t b0h = bh[j >> 1][(j & 1) * 2], b1h = bh[j >> 1][(j & 1) * 2 + 1];
                    uint32_t b0l = bl[j >> 1][(j & 1) * 2], b1l = bl[j >> 1][(j & 1) * 2 + 1];
                    mma16816(acc[mi][j], ah, b0h, b1h);
                    mma16816(acc[mi][j], ah, b0l, b1l);
                    mma16816(acc[mi][j], al, b0h, b1h);
                }
            }
        }
        __syncthreads();
    }

    const int lr = lane >> 2;
    const int lc = (lane & 3) * 2;
    #pragma unroll
    for (int mi = 0; mi < 4; mi++) {
        #pragma unroll
        for (int j = 0; j < 4; j++) {
            int row = mt * 128 + wm * 64 + mi * 16 + lr;
            int col = nb * 128 + wn * 32 + j * 8 + lc;
            if (mode == 1) {
                float2 bv = *(const float2*)(bias + col);
                *(float2*)(outp + (size_t)row * Cn + col) =
                    make_float2(acc[mi][j][0] + bv.x, acc[mi][j][1] + bv.y);
                *(float2*)(outp + (size_t)(row + 8) * Cn + col) =
                    make_float2(acc[mi][j][2] + bv.x, acc[mi][j][3] + bv.y);
            } else {
                int b = row >> 11, t = row & 2047;
                int h = col >> 6, d = col & 63;
                size_t off = ((size_t)((b << 4) + h) * Tn + t) * Dn + d;
                if (z == 2) {
                    *(float2*)(g_v + off) = make_float2(acc[mi][j][0], acc[mi][j][1]);
                    *(float2*)(g_v + off + 8 * Dn) = make_float2(acc[mi][j][2], acc[mi][j][3]);
                } else {
                    const float sc = (z == 0) ? 0.03125f : 1.0f;
                    __nv_bfloat16* dh = (z == 0) ? g_qhi : g_khi;
                    __nv_bfloat16* dl = (z == 0) ? g_qlo : g_klo;
                    uint32_t h0, l0, h1, l1;
                    split_pack(acc[mi][j][0] * sc, acc[mi][j][1] * sc, h0, l0);
                    split_pack(acc[mi][j][2] * sc, acc[mi][j][3] * sc, h1, l1);
                    *(uint32_t*)(dh + off) = h0;
                    *(uint32_t*)(dl + off) = l0;
                    *(uint32_t*)(dh + off + 8 * Dn) = h1;
                    *(uint32_t*)(dl + off + 8 * Dn) = l1;
                }
            }
        }
    }
}

// ---------------------------------------------------------------------------
// HMMA flash attention (bf16x3 QK + PV, FMA-pipe exp).
// Grid (T/128, B*H), 256 threads = 8 warps, each warp owns 16 query rows.
// Key blocks of 64. Q frags register-resident; K/V double-buffered cp.async.
// ---------------------------------------------------------------------------
#define AT_PITCH 144                 // 64 bf16 (128 B) + 16 B pad
#define AT_TILE  (64*AT_PITCH)       // 9216
#define AT_STAGE (4*AT_TILE)         // 36864: Kh, Kl, Vh, Vl
#define AT_SMEM  (2*AT_STAGE)        // 73728

__device__ __forceinline__ void at_load_kv(uint32_t dstbase,
    const __nv_bfloat16* __restrict__ Kh, const __nv_bfloat16* __restrict__ Kl,
    const __nv_bfloat16* __restrict__ Vth, const __nv_bfloat16* __restrict__ Vtl,
    int jt, int tid)
{
    const int koff = jt * 64;
    #pragma unroll
    for (int i = 0; i < 8; i++) {
        int c = tid + i * 256;           // 0..2047
        int arr = c >> 9;                // 0..3 (constant per i half)
        int cc = c & 511;
        int row = cc >> 3, o = cc & 7;
        const __nv_bfloat16* g;
        size_t goff;
        if (arr == 0)      { g = Kh;  goff = (size_t)(koff + row) * Dn + o * 8; }
        else if (arr == 1) { g = Kl;  goff = (size_t)(koff + row) * Dn + o * 8; }
        else if (arr == 2) { g = Vth; goff = (size_t)row * Tn + koff + o * 8; }
        else               { g = Vtl; goff = (size_t)row * Tn + koff + o * 8; }
        cp16(dstbase + arr * AT_TILE + row * AT_PITCH + o * 16, g + goff);
    }
}

__global__ __launch_bounds__(256, 1) void attn_mma()
{
    extern __shared__ __align__(128) char smem[];
    const uint32_t sb = smem_to_u32(smem);
    const int tid = threadIdx.x;
    const int lane = tid & 31, wid = tid >> 5;
    const int qt = blockIdx.x, bh = blockIdx.y;
    const int b = bh >> 4, h = bh & 15;

    const __nv_bfloat16* Qh = g_qhi + ((size_t)bh * Tn + qt * 128) * Dn;
    const __nv_bfloat16* Ql = g_qlo + ((size_t)bh * Tn + qt * 128) * Dn;
    const __nv_bfloat16* Kh = g_khi + (size_t)bh * Tn * Dn;
    const __nv_bfloat16* Kl = g_klo + (size_t)bh * Tn * Dn;
    const __nv_bfloat16* Vth = g_vthi + (size_t)bh * Dn * Tn;
    const __nv_bfloat16* Vtl = g_vtlo + (size_t)bh * Dn * Tn;

    // --- stage Q through smem (stage-0 region), ldmatrix into registers ---
    #pragma unroll
    for (int i = 0; i < 8; i++) {
        int c = tid + i * 256;           // 0..2047 (2 tiles x 1024 chunks)
        int arr = c >> 10;               // 0: hi, 1: lo
        int cc = c & 1023;
        int row = cc >> 3, o = cc & 7;
        const __nv_bfloat16* g = (arr ? Ql : Qh) + (size_t)row * Dn + o * 8;
        cp16(sb + arr * (128 * AT_PITCH) + row * AT_PITCH + o * 16, g);
    }
    cp_commit();
    asm volatile("cp.async.wait_group 0;" ::: "memory");
    __syncthreads();

    uint32_t qh[4][4], ql[4][4];
    {
        uint32_t abase = sb + (wid * 16 + (lane & 15)) * AT_PITCH + ((lane >> 4) << 4);
        #pragma unroll
        for (int kk = 0; kk < 4; kk++) {
            ldsm4(qh[kk], abase + kk * 32);
            ldsm4(ql[kk], abase + 128 * AT_PITCH + kk * 32);
        }
    }
    __syncthreads();   // Q consumed; stage-0 region reusable

    const uint32_t b_noff = ((lane >> 4) << 3) + (lane & 7);
    const uint32_t b_kb   = ((lane >> 3) & 1) << 4;

    float o_[8][4] = {};
    float m0 = -1e30f, m1 = -1e30f, l0 = 0.0f, l1 = 0.0f;

    const int jmax = 2 * qt + 1;
    at_load_kv(sb, Kh, Kl, Vth, Vtl, 0, tid);
    cp_commit();

    for (int jt = 0; jt <= jmax; jt++) {
        const int stg = jt & 1;
        if (jt < jmax) {
            at_load_kv(sb + (stg ^ 1) * AT_STAGE, Kh, Kl, Vth, Vtl, jt + 1, tid);
            cp_commit();
            asm volatile("cp.async.wait_group 1;" ::: "memory");
        } else {
            asm volatile("cp.async.wait_group 0;" ::: "memory");
        }
        __syncthreads();

        const uint32_t s0 = sb + stg * AT_STAGE;

        // ---- scores S = Qs @ K^T (bf16x3) ----
        float s[8][4];
        #pragma unroll
        for (int j = 0; j < 8; j++)
            #pragma unroll
            for (int c = 0; c < 4; c++) s[j][c] = 0.0f;

        #pragma unroll
        for (int j = 0; j < 4; j++) {
            #pragma unroll
            for (int kk = 0; kk < 4; kk++) {
                uint32_t kh4[4], kl4[4];
                uint32_t addr = s0 + (j * 16 + b_noff) * AT_PITCH + kk * 32 + b_kb;
                ldsm4(kh4, addr);
                ldsm4(kl4, addr + AT_TILE);
                mma16816(s[2*j],   qh[kk], kh4[0], kh4[1]);
                mma16816(s[2*j],   qh[kk], kl4[0], kl4[1]);
                mma16816(s[2*j],   ql[kk], kh4[0], kh4[1]);
                mma16816(s[2*j+1], qh[kk], kh4[2], kh4[3]);
                mma16816(s[2*j+1], qh[kk], kl4[2], kl4[3]);
                mma16816(s[2*j+1], ql[kk], kh4[2], kh4[3]);
            }
        }

        // ---- causal mask ----
        const int r0 = qt * 128 + wid * 16 + (lane >> 2);
        const int r1 = r0 + 8;
        if (jt >= 2 * qt) {
            #pragma unroll
            for (int j = 0; j < 8; j++) {
                int kc = jt * 64 + j * 8 + 2 * (lane & 3);
                if (kc     > r0) s[j][0] = -1e30f;
                if (kc + 1 > r0) s[j][1] = -1e30f;
                if (kc     > r1) s[j][2] = -1e30f;
                if (kc + 1 > r1) s[j][3] = -1e30f;
            }
        }

        // ---- online softmax (FMA-pipe exp) ----
        float mt0 = -1e30f, mt1 = -1e30f;
        #pragma unroll
        for (int j = 0; j < 8; j++) {
            mt0 = fmaxf(mt0, fmaxf(s[j][0], s[j][1]));
            mt1 = fmaxf(mt1, fmaxf(s[j][2], s[j][3]));
        }
        mt0 = fmaxf(mt0, __shfl_xor_sync(0xffffffffu, mt0, 1));
        mt0 = fmaxf(mt0, __shfl_xor_sync(0xffffffffu, mt0, 2));
        mt1 = fmaxf(mt1, __shfl_xor_sync(0xffffffffu, mt1, 1));
        mt1 = fmaxf(mt1, __shfl_xor_sync(0xffffffffu, mt1, 2));

        float mn0 = fmaxf(m0, mt0), mn1 = fmaxf(m1, mt1);
        float al0 = fexp(m0 - mn0), al1 = fexp(m1 - mn1);
        m0 = mn0; m1 = mn1;
        l0 *= al0; l1 *= al1;
        #pragma unroll
        for (int j = 0; j < 8; j++) {
            o_[j][0] *= al0; o_[j][1] *= al0;
            o_[j][2] *= al1; o_[j][3] *= al1;
        }
        float rs0 = 0.0f, rs1 = 0.0f;
        #pragma unroll
        for (int j = 0; j < 8; j++) {
            s[j][0] = fexp(s[j][0] - mn0); rs0 += s[j][0];
            s[j][1] = fexp(s[j][1] - mn0); rs0 += s[j][1];
            s[j][2] = fexp(s[j][2] - mn1); rs1 += s[j][2];
            s[j][3] = fexp(s[j][3] - mn1); rs1 += s[j][3];
        }
        rs0 += __shfl_xor_sync(0xffffffffu, rs0, 1);
        rs0 += __shfl_xor_sync(0xffffffffu, rs0, 2);
        rs1 += __shfl_xor_sync(0xffffffffu, rs1, 1);
        rs1 += __shfl_xor_sync(0xffffffffu, rs1, 2);
        l0 += rs0; l1 += rs1;

        // ---- pack P into A fragments (hi/lo) ----
        uint32_t ph[4][4], pl[4][4];
        #pragma unroll
        for (int kk = 0; kk < 4; kk++) {
            split_pack(s[2*kk][0],   s[2*kk][1],   ph[kk][0], pl[kk][0]);
            split_pack(s[2*kk][2],   s[2*kk][3],   ph[kk][1], pl[kk][1]);
            split_pack(s[2*kk+1][0], s[2*kk+1][1], ph[kk][2], pl[kk][2]);
            split_pack(s[2*kk+1][2], s[2*kk+1][3], ph[kk][3], pl[kk][3]);
        }

        // ---- O += P @ V (bf16x3) ----
        #pragma unroll
        for (int jd = 0; jd < 4; jd++) {
            #pragma unroll
            for (int kk = 0; kk < 4; kk++) {
                uint32_t vh4[4], vl4[4];
                uint32_t addr = s0 + 2 * AT_TILE + (jd * 16 + b_noff) * AT_PITCH
                                + kk * 32 + b_kb;
                ldsm4(vh4, addr);
                ldsm4(vl4, addr + AT_TILE);
                mma16816(o_[2*jd],   ph[kk], vh4[0], vh4[1]);
                mma16816(o_[2*jd],   ph[kk], vl4[0], vl4[1]);
                mma16816(o_[2*jd],   pl[kk], vh4[0], vh4[1]);
                mma16816(o_[2*jd+1], ph[kk], vh4[2], vh4[3]);
                mma16816(o_[2*jd+1], ph[kk], vl4[2], vl4[3]);
                mma16816(o_[2*jd+1], pl[kk], vh4[2], vh4[3]);
            }
        }
        __syncthreads();
    }

    // ---- epilogue: normalize + write [B][T][H*D] ----
    const float inv0 = 1.0f / l0, inv1 = 1.0f / l1;
    const int r0 = qt * 128 + wid * 16 + (lane >> 2);
    float* dst = g_att + ((size_t)b * Tn + r0) * Cn + h * 64;
    #pragma unroll
    for (int j = 0; j < 8; j++) {
        int d = j * 8 + 2 * (lane & 3);
        *(float2*)(dst + d) = make_float2(o_[j][0] * inv0, o_[j][1] * inv0);
        *(float2*)(dst + 8 * Cn + d) = make_float2(o_[j][2] * inv1, o_[j][3] * inv1);
    }
}

// ---------------------------------------------------------------------------
extern "C" void kernel_launch(void* const* d_in, const int* in_sizes, int n_in,
                              void* d_out, int out_size)
{
    const float* x      = (const float*)d_in[0];
    const float* wq     = (const float*)d_in[1];
    const float* wk     = (const float*)d_in[2];
    const float* wv     = (const float*)d_in[3];
    const float* w_proj = (const float*)d_in[4];
    const float* b_proj = (const float*)d_in[5];
    float* out = (float*)d_out;

    cudaFuncSetAttribute(gemm_hmma,
                         cudaFuncAttributeMaxDynamicSharedMemorySize, GSMEM);
    cudaFuncSetAttribute(attn_mma,
                         cudaFuncAttributeMaxDynamicSharedMemorySize, AT_SMEM);

    // 1) split x -> bf16 hi/lo
    int n4 = Mrows * Cn / 4;
    split_kernel<<<(n4 + 255) / 256, 256>>>(x, 0);

    // 2) transpose + split weights
    transpose_split_k<<<dim3(Dn/32, Cn/32, Hn), dim3(32,8)>>>(wq, Cn, Dn, 0);
    transpose_split_k<<<dim3(Dn/32, Cn/32, Hn), dim3(32,8)>>>(wk, Cn, Dn, 1);
    transpose_split_k<<<dim3(Dn/32, Cn/32, Hn), dim3(32,8)>>>(wv, Cn, Dn, 2);
    transpose_split_k<<<dim3(Cn/32, Cn/32, 1),  dim3(32,8)>>>(w_proj, Cn, Cn, 3);

    // 3) QKV GEMMs (q/k -> bf16 hi/lo directly, v -> fp32)
    gemm_hmma<<<dim3(Cn/128, Mrows/128, 3), 256, GSMEM>>>(nullptr, nullptr, 0);

    // 4) V transpose+split for PV B-operand
    v_transpose_split<<<dim3(Tn/32, Dn/32, Bn*Hn), dim3(32,8)>>>();

    // 5) attention (HMMA flash, bf16x3)
    attn_mma<<<dim3(Tn/128, Bn*Hn), 256, AT_SMEM>>>();

    // 6) split attention output -> bf16 hi/lo
    split_kernel<<<(n4 + 255) / 256, 256>>>(nullptr, 1);

    // 7) output projection (+bias)
    gemm_hmma<<<dim3(Cn/128, Mrows/128, 1), 256, GSMEM>>>(b_proj, out, 1);
}

// round 6
// speedup vs baseline: 3.3333x; 1.3145x over previous
#include <cuda_runtime.h>
#include <cuda_bf16.h>
#include <cuda_fp16.h>
#include <cstdint>

// Problem constants
#define Bn 4
#define Tn 2048
#define Cn 1024
#define Hn 16
#define Dn 64
#define Mrows (Bn*Tn)   // 8192

// ---------------------------------------------------------------------------
// Scratch (allocation-free rule: __device__ globals), 16B-aligned
// ---------------------------------------------------------------------------
__device__ __align__(16) float g_v[Bn*Hn*Tn*Dn];            // [B*H][T][D] fp32

__device__ __align__(16) __nv_bfloat16 g_qhi[Bn*Hn*Tn*Dn];  // [B*H][T][D], pre-scaled
__device__ __align__(16) __nv_bfloat16 g_qlo[Bn*Hn*Tn*Dn];
__device__ __align__(16) __nv_bfloat16 g_khi[Bn*Hn*Tn*Dn];
__device__ __align__(16) __nv_bfloat16 g_klo[Bn*Hn*Tn*Dn];
__device__ __align__(16) __nv_bfloat16 g_vthi[Bn*Hn*Dn*Tn]; // [B*H][D][T] (V^T)
__device__ __align__(16) __nv_bfloat16 g_vtlo[Bn*Hn*Dn*Tn];

__device__ __align__(16) __half g_x16[Mrows*Cn];            // x as fp16
__device__ __align__(16) __half g_wt16[3*Cn*Cn];            // qkv weights [3][N][K] fp16

__device__ __align__(16) __nv_bfloat16 g_wpt_hi[Cn*Cn];     // w_proj^T [N][K] bf16 hi/lo
__device__ __align__(16) __nv_bfloat16 g_wpt_lo[Cn*Cn];
__device__ __align__(16) __nv_bfloat16 g_atthi[Mrows*Cn];   // attention out [B][T][H*D]
__device__ __align__(16) __nv_bfloat16 g_attlo[Mrows*Cn];

// ---------------------------------------------------------------------------
// PTX helpers (sm_100-portable)
// ---------------------------------------------------------------------------
__device__ __forceinline__ uint32_t smem_to_u32(const void* p) {
    uint32_t a;
    asm("{ .reg .u64 t; cvta.to.shared.u64 t, %1; cvt.u32.u64 %0, t; }"
        : "=r"(a) : "l"(p));
    return a;
}
__device__ __forceinline__ void cp16(uint32_t dst, const void* src) {
    asm volatile("cp.async.cg.shared.global [%0], [%1], 16;"
                 :: "r"(dst), "l"(src) : "memory");
}
__device__ __forceinline__ void cp_commit() {
    asm volatile("cp.async.commit_group;" ::: "memory");
}
__device__ __forceinline__ void ldsm4(uint32_t (&r)[4], uint32_t addr) {
    asm volatile("ldmatrix.sync.aligned.m8n8.x4.shared.b16 {%0,%1,%2,%3}, [%4];"
                 : "=r"(r[0]), "=r"(r[1]), "=r"(r[2]), "=r"(r[3]) : "r"(addr));
}
__device__ __forceinline__ void mma16816(float (&c)[4], const uint32_t (&a)[4],
                                         uint32_t b0, uint32_t b1) {
    asm volatile(
        "mma.sync.aligned.m16n8k16.row.col.f32.bf16.bf16.f32 "
        "{%0,%1,%2,%3}, {%4,%5,%6,%7}, {%8,%9}, {%0,%1,%2,%3};"
        : "+f"(c[0]), "+f"(c[1]), "+f"(c[2]), "+f"(c[3])
        : "r"(a[0]), "r"(a[1]), "r"(a[2]), "r"(a[3]), "r"(b0), "r"(b1));
}
__device__ __forceinline__ void mma16816h(float (&c)[4], const uint32_t (&a)[4],
                                          uint32_t b0, uint32_t b1) {
    asm volatile(
        "mma.sync.aligned.m16n8k16.row.col.f32.f16.f16.f32 "
        "{%0,%1,%2,%3}, {%4,%5,%6,%7}, {%8,%9}, {%0,%1,%2,%3};"
        : "+f"(c[0]), "+f"(c[1]), "+f"(c[2]), "+f"(c[3])
        : "r"(a[0]), "r"(a[1]), "r"(a[2]), "r"(a[3]), "r"(b0), "r"(b1));
}

// Fast exp on the FMA/ALU pipes (no MUFU). rel err ~3e-6. Handles -1e30 -> ~0.
__device__ __forceinline__ float fexp(float x) {
    float y = x * 1.4426950408889634f;
    y = fmaxf(y, -126.0f);
    float r = y + 12582912.0f;
    float n = r - 12582912.0f;
    float f = y - n;
    int   e = __float_as_int(r);
    float u = f * 0.6931471805599453f;
    float p = 8.3333333e-3f;
    p = fmaf(p, u, 4.1666667e-2f);
    p = fmaf(p, u, 1.6666667e-1f);
    p = fmaf(p, u, 5.0e-1f);
    p = fmaf(p, u, 1.0f);
    p = fmaf(p, u, 1.0f);
    int sc = (e - 0x4B400000 + 127) << 23;
    return __int_as_float(sc) * p;
}

__device__ __forceinline__ void split_pack(float a, float b,
                                           uint32_t& hi, uint32_t& lo) {
    __nv_bfloat16 ha = __float2bfloat16(a);
    __nv_bfloat16 hb = __float2bfloat16(b);
    __nv_bfloat16 la = __float2bfloat16(a - __bfloat162float(ha));
    __nv_bfloat16 lb = __float2bfloat16(b - __bfloat162float(hb));
    __nv_bfloat162 H(ha, hb), L(la, lb);
    hi = *reinterpret_cast<uint32_t*>(&H);
    lo = *reinterpret_cast<uint32_t*>(&L);
}

// ---------------------------------------------------------------------------
// x fp32 -> fp16
// ---------------------------------------------------------------------------
__global__ void x_to_f16(const float* __restrict__ x)
{
    int i = blockIdx.x * blockDim.x + threadIdx.x;
    if (i >= Mrows * Cn / 4) return;
    float4 v = ((const float4*)x)[i];
    __half2 a(__float2half(v.x), __float2half(v.y));
    __half2 b(__float2half(v.z), __float2half(v.w));
    *(__half2*)(g_x16 + (size_t)i*4)     = a;
    *(__half2*)(g_x16 + (size_t)i*4 + 2) = b;
}

// ---------------------------------------------------------------------------
// QKV weights: [H][C][D] fp32 -> g_wt16 [sel][H*D rows][C] fp16 (transposed)
// Grid (Dn/32, Cn/32, Hn), block (32,8)
// ---------------------------------------------------------------------------
__global__ void transpose_w_f16(const float* __restrict__ in, int sel)
{
    __shared__ float t[32][33];
    const int z = blockIdx.z;
    const float* src = in + (size_t)z * Cn * Dn;
    __half* dst = g_wt16 + (size_t)sel * Cn * Cn + (size_t)z * Dn * Cn;
    const int c0 = blockIdx.x * 32, r0 = blockIdx.y * 32;
    const int tx = threadIdx.x, ty = threadIdx.y;
    #pragma unroll
    for (int j = 0; j < 4; j++)
        t[ty + 8*j][tx] = src[(size_t)(r0 + ty + 8*j) * Dn + c0 + tx];
    __syncthreads();
    #pragma unroll
    for (int j = 0; j < 4; j++)
        dst[(size_t)(c0 + ty + 8*j) * Cn + r0 + tx] = __float2half(t[tx][ty + 8*j]);
}

// ---------------------------------------------------------------------------
// w_proj [C][C] fp32 -> g_wpt hi/lo [N][K] bf16 (transposed)
// Grid (Cn/32, Cn/32), block (32,8)
// ---------------------------------------------------------------------------
__global__ void transpose_wproj(const float* __restrict__ in)
{
    __shared__ float t[32][33];
    const int c0 = blockIdx.x * 32, r0 = blockIdx.y * 32;
    const int tx = threadIdx.x, ty = threadIdx.y;
    #pragma unroll
    for (int j = 0; j < 4; j++)
        t[ty + 8*j][tx] = in[(size_t)(r0 + ty + 8*j) * Cn + c0 + tx];
    __syncthreads();
    #pragma unroll
    for (int j = 0; j < 4; j++) {
        float a = t[tx][ty + 8*j];
        __nv_bfloat16 h = __float2bfloat16(a);
        size_t o = (size_t)(c0 + ty + 8*j) * Cn + r0 + tx;
        g_wpt_hi[o] = h;
        g_wpt_lo[o] = __float2bfloat16(a - __bfloat162float(h));
    }
}

// ---------------------------------------------------------------------------
// V transpose+split: g_v [BH][T][D] fp32 -> g_vthi/lo [BH][D][T] bf16
// ---------------------------------------------------------------------------
__global__ void v_transpose_split()
{
    __shared__ float t[32][33];
    const int z = blockIdx.z;
    const int t0 = blockIdx.x * 32, d0 = blockIdx.y * 32;
    const float* src = g_v + (size_t)z * Tn * Dn;
    __nv_bfloat16* dhi = g_vthi + (size_t)z * Dn * Tn;
    __nv_bfloat16* dlo = g_vtlo + (size_t)z * Dn * Tn;
    const int tx = threadIdx.x, ty = threadIdx.y;
    #pragma unroll
    for (int j = 0; j < 4; j++)
        t[ty + 8*j][tx] = src[(size_t)(t0 + ty + 8*j) * Dn + d0 + tx];
    __syncthreads();
    #pragma unroll
    for (int j = 0; j < 4; j++) {
        float a = t[tx][ty + 8*j];
        __nv_bfloat16 h = __float2bfloat16(a);
        size_t o = (size_t)(d0 + ty + 8*j) * Tn + t0 + tx;
        dhi[o] = h;
        dlo[o] = __float2bfloat16(a - __bfloat162float(h));
    }
}

// ---------------------------------------------------------------------------
// Shared GEMM geometry
// ---------------------------------------------------------------------------
#define KPITCH 40
#define ROWB   (KPITCH*2)         // 80 B
#define TILEB  (128*ROWB)         // 10240 B
#define NCHUNK (Cn/32)            // 32

// ---------------------------------------------------------------------------
// fp16 single-pass QKV GEMM: q/k/v[8192,1024] = x16 * wt16^T
// z=0: q (scaled, split to bf16 hi/lo), z=1: k (split), z=2: v (fp32)
// ---------------------------------------------------------------------------
#define STAGE2 (2*TILEB)          // A + B
#define GSMEM2 (2*STAGE2)         // 40960

__device__ __forceinline__ void load_chunk2(uint32_t sbase,
    const __half* __restrict__ Ag, const __half* __restrict__ Bg,
    int k0, int tid)
{
    const __half* gsrc[2] = {Ag, Bg};
    #pragma unroll
    for (int a = 0; a < 2; a++) {
        #pragma unroll
        for (int j = 0; j < 2; j++) {
            int o = tid + j * 256;
            int row = o >> 2, ch = o & 3;
            cp16(sbase + a * TILEB + row * ROWB + ch * 16,
                 gsrc[a] + (size_t)row * Cn + k0 + ch * 8);
        }
    }
}

__global__ __launch_bounds__(256) void gemm_f16_qkv()
{
    extern __shared__ __align__(128) char smem[];
    const uint32_t smem_base = smem_to_u32(smem);
    const int tid = threadIdx.x;
    const int lane = tid & 31, wid = tid >> 5;
    const int wm = wid >> 2, wn = wid & 3;
    const int nb = blockIdx.x, mt = blockIdx.y, z = blockIdx.z;

    const __half* Ag = g_x16 + (size_t)mt * 128 * Cn;
    const __half* Bg = g_wt16 + (size_t)z * Cn * Cn + (size_t)nb * 128 * Cn;

    float acc[4][4][4] = {};
    const uint32_t a_row  = (lane & 15);
    const uint32_t a_kb   = (lane >> 4) << 4;
    const uint32_t b_noff = ((lane >> 4) << 3) + (lane & 7);
    const uint32_t b_kb   = ((lane >> 3) & 1) << 4;

    load_chunk2(smem_base, Ag, Bg, 0, tid);
    cp_commit();

    for (int i = 0; i < NCHUNK; i++) {
        const int buf = i & 1;
        if (i + 1 < NCHUNK) {
            load_chunk2(smem_base + (buf ^ 1) * STAGE2, Ag, Bg, (i + 1) * 32, tid);
            cp_commit();
            asm volatile("cp.async.wait_group 1;" ::: "memory");
        } else {
            asm volatile("cp.async.wait_group 0;" ::: "memory");
        }
        __syncthreads();

        const uint32_t sb = smem_base + buf * STAGE2;
        #pragma unroll
        for (int ks = 0; ks < 2; ks++) {
            uint32_t bb[2][4];
            #pragma unroll
            for (int p = 0; p < 2; p++) {
                uint32_t n = wn * 32 + p * 16 + b_noff;
                ldsm4(bb[p], sb + TILEB + n * ROWB + ks * 32 + b_kb);
            }
            #pragma unroll
            for (int mi = 0; mi < 4; mi++) {
                uint32_t r = wm * 64 + mi * 16 + a_row;
                uint32_t aa[4];
                ldsm4(aa, sb + r * ROWB + ks * 32 + a_kb);
                #pragma unroll
                for (int j = 0; j < 4; j++)
                    mma16816h(acc[mi][j], aa,
                              bb[j >> 1][(j & 1) * 2], bb[j >> 1][(j & 1) * 2 + 1]);
            }
        }
        __syncthreads();
    }

    const int lr = lane >> 2;
    const int lc = (lane & 3) * 2;
    #pragma unroll
    for (int mi = 0; mi < 4; mi++) {
        #pragma unroll
        for (int j = 0; j < 4; j++) {
            int row = mt * 128 + wm * 64 + mi * 16 + lr;
            int col = nb * 128 + wn * 32 + j * 8 + lc;
            int b = row >> 11, t = row & 2047;
            int h = col >> 6, d = col & 63;
            size_t off = ((size_t)((b << 4) + h) * Tn + t) * Dn + d;
            if (z == 2) {
                *(float2*)(g_v + off) = make_float2(acc[mi][j][0], acc[mi][j][1]);
                *(float2*)(g_v + off + 8 * Dn) = make_float2(acc[mi][j][2], acc[mi][j][3]);
            } else {
                const float sc = (z == 0) ? 0.03125f : 1.0f;
                __nv_bfloat16* dh = (z == 0) ? g_qhi : g_khi;
                __nv_bfloat16* dl = (z == 0) ? g_qlo : g_klo;
                uint32_t h0, l0, h1, l1;
                split_pack(acc[mi][j][0] * sc, acc[mi][j][1] * sc, h0, l0);
                split_pack(acc[mi][j][2] * sc, acc[mi][j][3] * sc, h1, l1);
                *(uint32_t*)(dh + off) = h0;
                *(uint32_t*)(dl + off) = l0;
                *(uint32_t*)(dh + off + 8 * Dn) = h1;
                *(uint32_t*)(dl + off + 8 * Dn) = l1;
            }
        }
    }
}

// ---------------------------------------------------------------------------
// bf16x3 proj GEMM: out[8192,1024] = att * w_proj + bias
// A = g_atthi/lo [M][K], B = g_wpt_hi/lo [N][K]
// ---------------------------------------------------------------------------
#define STAGEB (4*TILEB)
#define GSMEM  (2*STAGEB)         // 81920

__device__ __forceinline__ void load_chunk4(uint32_t sbase,
    const __nv_bfloat16* __restrict__ Ah, const __nv_bfloat16* __restrict__ Al,
    const __nv_bfloat16* __restrict__ Bh, const __nv_bfloat16* __restrict__ Bl,
    int k0, int tid)
{
    const __nv_bfloat16* gsrc[4] = {Ah, Al, Bh, Bl};
    #pragma unroll
    for (int a = 0; a < 4; a++) {
        #pragma unroll
        for (int j = 0; j < 2; j++) {
            int o = tid + j * 256;
            int row = o >> 2, ch = o & 3;
            cp16(sbase + a * TILEB + row * ROWB + ch * 16,
                 gsrc[a] + (size_t)row * Cn + k0 + ch * 8);
        }
    }
}

__global__ __launch_bounds__(256) void gemm_proj(
    const float* __restrict__ bias, float* __restrict__ outp)
{
    extern __shared__ __align__(128) char smem[];
    const uint32_t smem_base = smem_to_u32(smem);
    const int tid = threadIdx.x;
    const int lane = tid & 31, wid = tid >> 5;
    const int wm = wid >> 2, wn = wid & 3;
    const int nb = blockIdx.x, mt = blockIdx.y;

    const __nv_bfloat16* Agh = g_atthi + (size_t)mt * 128 * Cn;
    const __nv_bfloat16* Agl = g_attlo + (size_t)mt * 128 * Cn;
    const __nv_bfloat16* Bgh = g_wpt_hi + (size_t)nb * 128 * Cn;
    const __nv_bfloat16* Bgl = g_wpt_lo + (size_t)nb * 128 * Cn;

    float acc[4][4][4] = {};
    const uint32_t a_row  = (lane & 15);
    const uint32_t a_kb   = (lane >> 4) << 4;
    const uint32_t b_noff = ((lane >> 4) << 3) + (lane & 7);
    const uint32_t b_kb   = ((lane >> 3) & 1) << 4;

    load_chunk4(smem_base, Agh, Agl, Bgh, Bgl, 0, tid);
    cp_commit();

    for (int i = 0; i < NCHUNK; i++) {
        const int buf = i & 1;
        if (i + 1 < NCHUNK) {
            load_chunk4(smem_base + (buf ^ 1) * STAGEB, Agh, Agl, Bgh, Bgl,
                        (i + 1) * 32, tid);
            cp_commit();
            asm volatile("cp.async.wait_group 1;" ::: "memory");
        } else {
            asm volatile("cp.async.wait_group 0;" ::: "memory");
        }
        __syncthreads();

        const uint32_t sb = smem_base + buf * STAGEB;
        #pragma unroll
        for (int ks = 0; ks < 2; ks++) {
            uint32_t bh[2][4], bl[2][4];
            #pragma unroll
            for (int p = 0; p < 2; p++) {
                uint32_t n = wn * 32 + p * 16 + b_noff;
                uint32_t off = n * ROWB + ks * 32 + b_kb;
                ldsm4(bh[p], sb + 2 * TILEB + off);
                ldsm4(bl[p], sb + 3 * TILEB + off);
            }
            #pragma unroll
            for (int mi = 0; mi < 4; mi++) {
                uint32_t r = wm * 64 + mi * 16 + a_row;
                uint32_t off = r * ROWB + ks * 32 + a_kb;
                uint32_t ah[4], al[4];
                ldsm4(ah, sb + off);
                ldsm4(al, sb + TILEB + off);
                #pragma unroll
                for (int j = 0; j < 4; j++) {
                    uint32_t b0h = bh[j >> 1][(j & 1) * 2], b1h = bh[j >> 1][(j & 1) * 2 + 1];
                    uint32_t b0l = bl[j >> 1][(j & 1) * 2], b1l = bl[j >> 1][(j & 1) * 2 + 1];
                    mma16816(acc[mi][j], ah, b0h, b1h);
                    mma16816(acc[mi][j], ah, b0l, b1l);
                    mma16816(acc[mi][j], al, b0h, b1h);
                }
            }
        }
        __syncthreads();
    }

    const int lr = lane >> 2;
    const int lc = (lane & 3) * 2;
    #pragma unroll
    for (int mi = 0; mi < 4; mi++) {
        #pragma unroll
        for (int j = 0; j < 4; j++) {
            int row = mt * 128 + wm * 64 + mi * 16 + lr;
            int col = nb * 128 + wn * 32 + j * 8 + lc;
            float2 bv = *(const float2*)(bias + col);
            *(float2*)(outp + (size_t)row * Cn + col) =
                make_float2(acc[mi][j][0] + bv.x, acc[mi][j][1] + bv.y);
            *(float2*)(outp + (size_t)(row + 8) * Cn + col) =
                make_float2(acc[mi][j][2] + bv.x, acc[mi][j][3] + bv.y);
        }
    }
}

// ---------------------------------------------------------------------------
// HMMA flash attention (bf16x3 QK + PV, FMA-pipe exp). Epilogue writes
// att directly as bf16 hi/lo in [B][T][H*D].
// ---------------------------------------------------------------------------
#define AT_PITCH 144
#define AT_TILE  (64*AT_PITCH)
#define AT_STAGE (4*AT_TILE)
#define AT_SMEM  (2*AT_STAGE)        // 73728

__device__ __forceinline__ void at_load_kv(uint32_t dstbase,
    const __nv_bfloat16* __restrict__ Kh, const __nv_bfloat16* __restrict__ Kl,
    const __nv_bfloat16* __restrict__ Vth, const __nv_bfloat16* __restrict__ Vtl,
    int jt, int tid)
{
    const int koff = jt * 64;
    #pragma unroll
    for (int i = 0; i < 8; i++) {
        int c = tid + i * 256;
        int arr = c >> 9;
        int cc = c & 511;
        int row = cc >> 3, o = cc & 7;
        const __nv_bfloat16* g;
        size_t goff;
        if (arr == 0)      { g = Kh;  goff = (size_t)(koff + row) * Dn + o * 8; }
        else if (arr == 1) { g = Kl;  goff = (size_t)(koff + row) * Dn + o * 8; }
        else if (arr == 2) { g = Vth; goff = (size_t)row * Tn + koff + o * 8; }
        else               { g = Vtl; goff = (size_t)row * Tn + koff + o * 8; }
        cp16(dstbase + arr * AT_TILE + row * AT_PITCH + o * 16, g + goff);
    }
}

__global__ __launch_bounds__(256, 1) void attn_mma()
{
    extern __shared__ __align__(128) char smem[];
    const uint32_t sb = smem_to_u32(smem);
    const int tid = threadIdx.x;
    const int lane = tid & 31, wid = tid >> 5;
    const int qt = blockIdx.x, bh = blockIdx.y;
    const int b = bh >> 4, h = bh & 15;

    const __nv_bfloat16* Qh = g_qhi + ((size_t)bh * Tn + qt * 128) * Dn;
    const __nv_bfloat16* Ql = g_qlo + ((size_t)bh * Tn + qt * 128) * Dn;
    const __nv_bfloat16* Kh = g_khi + (size_t)bh * Tn * Dn;
    const __nv_bfloat16* Kl = g_klo + (size_t)bh * Tn * Dn;
    const __nv_bfloat16* Vth = g_vthi + (size_t)bh * Dn * Tn;
    const __nv_bfloat16* Vtl = g_vtlo + (size_t)bh * Dn * Tn;

    #pragma unroll
    for (int i = 0; i < 8; i++) {
        int c = tid + i * 256;
        int arr = c >> 10;
        int cc = c & 1023;
        int row = cc >> 3, o = cc & 7;
        const __nv_bfloat16* g = (arr ? Ql : Qh) + (size_t)row * Dn + o * 8;
        cp16(sb + arr * (128 * AT_PITCH) + row * AT_PITCH + o * 16, g);
    }
    cp_commit();
    asm volatile("cp.async.wait_group 0;" ::: "memory");
    __syncthreads();

    uint32_t qh[4][4], ql[4][4];
    {
        uint32_t abase = sb + (wid * 16 + (lane & 15)) * AT_PITCH + ((lane >> 4) << 4);
        #pragma unroll
        for (int kk = 0; kk < 4; kk++) {
            ldsm4(qh[kk], abase + kk * 32);
            ldsm4(ql[kk], abase + 128 * AT_PITCH + kk * 32);
        }
    }
    __syncthreads();

    const uint32_t b_noff = ((lane >> 4) << 3) + (lane & 7);
    const uint32_t b_kb   = ((lane >> 3) & 1) << 4;

    float o_[8][4] = {};
    float m0 = -1e30f, m1 = -1e30f, l0 = 0.0f, l1 = 0.0f;

    const int jmax = 2 * qt + 1;
    at_load_kv(sb, Kh, Kl, Vth, Vtl, 0, tid);
    cp_commit();

    for (int jt = 0; jt <= jmax; jt++) {
        const int stg = jt & 1;
        if (jt < jmax) {
            at_load_kv(sb + (stg ^ 1) * AT_STAGE, Kh, Kl, Vth, Vtl, jt + 1, tid);
            cp_commit();
            asm volatile("cp.async.wait_group 1;" ::: "memory");
        } else {
            asm volatile("cp.async.wait_group 0;" ::: "memory");
        }
        __syncthreads();

        const uint32_t s0 = sb + stg * AT_STAGE;

        float s[8][4];
        #pragma unroll
        for (int j = 0; j < 8; j++)
            #pragma unroll
            for (int c = 0; c < 4; c++) s[j][c] = 0.0f;

        #pragma unroll
        for (int j = 0; j < 4; j++) {
            #pragma unroll
            for (int kk = 0; kk < 4; kk++) {
                uint32_t kh4[4], kl4[4];
                uint32_t addr = s0 + (j * 16 + b_noff) * AT_PITCH + kk * 32 + b_kb;
                ldsm4(kh4, addr);
                ldsm4(kl4, addr + AT_TILE);
                mma16816(s[2*j],   qh[kk], kh4[0], kh4[1]);
                mma16816(s[2*j],   qh[kk], kl4[0], kl4[1]);
                mma16816(s[2*j],   ql[kk], kh4[0], kh4[1]);
                mma16816(s[2*j+1], qh[kk], kh4[2], kh4[3]);
                mma16816(s[2*j+1], qh[kk], kl4[2], kl4[3]);
                mma16816(s[2*j+1], ql[kk], kh4[2], kh4[3]);
            }
        }

        const int r0 = qt * 128 + wid * 16 + (lane >> 2);
        const int r1 = r0 + 8;
        if (jt >= 2 * qt) {
            #pragma unroll
            for (int j = 0; j < 8; j++) {
                int kc = jt * 64 + j * 8 + 2 * (lane & 3);
                if (kc     > r0) s[j][0] = -1e30f;
                if (kc + 1 > r0) s[j][1] = -1e30f;
                if (kc     > r1) s[j][2] = -1e30f;
                if (kc + 1 > r1) s[j][3] = -1e30f;
            }
        }

        float mt0 = -1e30f, mt1 = -1e30f;
        #pragma unroll
        for (int j = 0; j < 8; j++) {
            mt0 = fmaxf(mt0, fmaxf(s[j][0], s[j][1]));
            mt1 = fmaxf(mt1, fmaxf(s[j][2], s[j][3]));
        }
        mt0 = fmaxf(mt0, __shfl_xor_sync(0xffffffffu, mt0, 1));
        mt0 = fmaxf(mt0, __shfl_xor_sync(0xffffffffu, mt0, 2));
        mt1 = fmaxf(mt1, __shfl_xor_sync(0xffffffffu, mt1, 1));
        mt1 = fmaxf(mt1, __shfl_xor_sync(0xffffffffu, mt1, 2));

        float mn0 = fmaxf(m0, mt0), mn1 = fmaxf(m1, mt1);
        float al0 = fexp(m0 - mn0), al1 = fexp(m1 - mn1);
        m0 = mn0; m1 = mn1;
        l0 *= al0; l1 *= al1;
        #pragma unroll
        for (int j = 0; j < 8; j++) {
            o_[j][0] *= al0; o_[j][1] *= al0;
            o_[j][2] *= al1; o_[j][3] *= al1;
        }
        float rs0 = 0.0f, rs1 = 0.0f;
        #pragma unroll
        for (int j = 0; j < 8; j++) {
            s[j][0] = fexp(s[j][0] - mn0); rs0 += s[j][0];
            s[j][1] = fexp(s[j][1] - mn0); rs0 += s[j][1];
            s[j][2] = fexp(s[j][2] - mn1); rs1 += s[j][2];
            s[j][3] = fexp(s[j][3] - mn1); rs1 += s[j][3];
        }
        rs0 += __shfl_xor_sync(0xffffffffu, rs0, 1);
        rs0 += __shfl_xor_sync(0xffffffffu, rs0, 2);
        rs1 += __shfl_xor_sync(0xffffffffu, rs1, 1);
        rs1 += __shfl_xor_sync(0xffffffffu, rs1, 2);
        l0 += rs0; l1 += rs1;

        uint32_t ph[4][4], pl[4][4];
        #pragma unroll
        for (int kk = 0; kk < 4; kk++) {
            split_pack(s[2*kk][0],   s[2*kk][1],   ph[kk][0], pl[kk][0]);
            split_pack(s[2*kk][2],   s[2*kk][3],   ph[kk][1], pl[kk][1]);
            split_pack(s[2*kk+1][0], s[2*kk+1][1], ph[kk][2], pl[kk][2]);
            split_pack(s[2*kk+1][2], s[2*kk+1][3], ph[kk][3], pl[kk][3]);
        }

        #pragma unroll
        for (int jd = 0; jd < 4; jd++) {
            #pragma unroll
            for (int kk = 0; kk < 4; kk++) {
                uint32_t vh4[4], vl4[4];
                uint32_t addr = s0 + 2 * AT_TILE + (jd * 16 + b_noff) * AT_PITCH
                                + kk * 32 + b_kb;
                ldsm4(vh4, addr);
                ldsm4(vl4, addr + AT_TILE);
                mma16816(o_[2*jd],   ph[kk], vh4[0], vh4[1]);
                mma16816(o_[2*jd],   ph[kk], vl4[0], vl4[1]);
                mma16816(o_[2*jd],   pl[kk], vh4[0], vh4[1]);
                mma16816(o_[2*jd+1], ph[kk], vh4[2], vh4[3]);
                mma16816(o_[2*jd+1], ph[kk], vl4[2], vl4[3]);
                mma16816(o_[2*jd+1], pl[kk], vh4[2], vh4[3]);
            }
        }
        __syncthreads();
    }

    // epilogue: normalize + write att as bf16 hi/lo [B][T][H*D]
    const float inv0 = 1.0f / l0, inv1 = 1.0f / l1;
    const int r0 = qt * 128 + wid * 16 + (lane >> 2);
    size_t off = ((size_t)b * Tn + r0) * Cn + h * 64;
    #pragma unroll
    for (int j = 0; j < 8; j++) {
        int d = j * 8 + 2 * (lane & 3);
        uint32_t h0, l0p, h1, l1p;
        split_pack(o_[j][0] * inv0, o_[j][1] * inv0, h0, l0p);
        split_pack(o_[j][2] * inv1, o_[j][3] * inv1, h1, l1p);
        *(uint32_t*)(g_atthi + off + d) = h0;
        *(uint32_t*)(g_attlo + off + d) = l0p;
        *(uint32_t*)(g_atthi + off + 8 * Cn + d) = h1;
        *(uint32_t*)(g_attlo + off + 8 * Cn + d) = l1p;
    }
}

// ---------------------------------------------------------------------------
extern "C" void kernel_launch(void* const* d_in, const int* in_sizes, int n_in,
                              void* d_out, int out_size)
{
    const float* x      = (const float*)d_in[0];
    const float* wq     = (const float*)d_in[1];
    const float* wk     = (const float*)d_in[2];
    const float* wv     = (const float*)d_in[3];
    const float* w_proj = (const float*)d_in[4];
    const float* b_proj = (const float*)d_in[5];
    float* out = (float*)d_out;

    cudaFuncSetAttribute(gemm_proj,
                         cudaFuncAttributeMaxDynamicSharedMemorySize, GSMEM);
    cudaFuncSetAttribute(attn_mma,
                         cudaFuncAttributeMaxDynamicSharedMemorySize, AT_SMEM);

    // 1) x -> fp16
    int n4 = Mrows * Cn / 4;
    x_to_f16<<<(n4 + 255) / 256, 256>>>(x);

    // 2) weights: qkv -> fp16 transposed; w_proj -> bf16 hi/lo transposed
    transpose_w_f16<<<dim3(Dn/32, Cn/32, Hn), dim3(32,8)>>>(wq, 0);
    transpose_w_f16<<<dim3(Dn/32, Cn/32, Hn), dim3(32,8)>>>(wk, 1);
    transpose_w_f16<<<dim3(Dn/32, Cn/32, Hn), dim3(32,8)>>>(wv, 2);
    transpose_wproj<<<dim3(Cn/32, Cn/32), dim3(32,8)>>>(w_proj);

    // 3) QKV GEMM (fp16 single-pass)
    gemm_f16_qkv<<<dim3(Cn/128, Mrows/128, 3), 256, GSMEM2>>>();

    // 4) V transpose+split
    v_transpose_split<<<dim3(Tn/32, Dn/32, Bn*Hn), dim3(32,8)>>>();

    // 5) attention (HMMA bf16x3); writes att bf16 hi/lo directly
    attn_mma<<<dim3(Tn/128, Bn*Hn), 256, AT_SMEM>>>();

    // 6) output projection (bf16x3, +bias)
    gemm_proj<<<dim3(Cn/128, Mrows/128), 256, GSMEM>>>(b_proj, out);
}

// round 7
// speedup vs baseline: 4.2522x; 1.2757x over previous
#include <cuda_runtime.h>
#include <cuda_bf16.h>
#include <cuda_fp16.h>
#include <cstdint>

// Problem constants
#define Bn 4
#define Tn 2048
#define Cn 1024
#define Hn 16
#define Dn 64
#define Mrows (Bn*Tn)   // 8192

// ---------------------------------------------------------------------------
// Scratch (allocation-free rule: __device__ globals), 16B-aligned
// ---------------------------------------------------------------------------
__device__ __align__(16) float g_v[Bn*Hn*Tn*Dn];            // [B*H][T][D] fp32

__device__ __align__(16) __half g_q16[Bn*Hn*Tn*Dn];         // [B*H][T][D], pre-scaled
__device__ __align__(16) __half g_k16[Bn*Hn*Tn*Dn];
__device__ __align__(16) __nv_bfloat16 g_vthi[Bn*Hn*Dn*Tn]; // [B*H][D][T] (V^T)
__device__ __align__(16) __nv_bfloat16 g_vtlo[Bn*Hn*Dn*Tn];

__device__ __align__(16) __half g_x16[Mrows*Cn];            // x as fp16
__device__ __align__(16) __half g_wt16[3*Cn*Cn];            // qkv weights [3][N][K] fp16
__device__ __align__(16) __half g_wp16[Cn*Cn];              // w_proj^T [N][K] fp16
__device__ __align__(16) __half g_att16[Mrows*Cn];          // attention out [B][T][H*D] fp16

// ---------------------------------------------------------------------------
// PTX helpers (sm_100-portable)
// ---------------------------------------------------------------------------
__device__ __forceinline__ uint32_t smem_to_u32(const void* p) {
    uint32_t a;
    asm("{ .reg .u64 t; cvta.to.shared.u64 t, %1; cvt.u32.u64 %0, t; }"
        : "=r"(a) : "l"(p));
    return a;
}
__device__ __forceinline__ void cp16(uint32_t dst, const void* src) {
    asm volatile("cp.async.cg.shared.global [%0], [%1], 16;"
                 :: "r"(dst), "l"(src) : "memory");
}
__device__ __forceinline__ void cp_commit() {
    asm volatile("cp.async.commit_group;" ::: "memory");
}
__device__ __forceinline__ void ldsm4(uint32_t (&r)[4], uint32_t addr) {
    asm volatile("ldmatrix.sync.aligned.m8n8.x4.shared.b16 {%0,%1,%2,%3}, [%4];"
                 : "=r"(r[0]), "=r"(r[1]), "=r"(r[2]), "=r"(r[3]) : "r"(addr));
}
__device__ __forceinline__ void mma16816(float (&c)[4], const uint32_t (&a)[4],
                                         uint32_t b0, uint32_t b1) {
    asm volatile(
        "mma.sync.aligned.m16n8k16.row.col.f32.bf16.bf16.f32 "
        "{%0,%1,%2,%3}, {%4,%5,%6,%7}, {%8,%9}, {%0,%1,%2,%3};"
        : "+f"(c[0]), "+f"(c[1]), "+f"(c[2]), "+f"(c[3])
        : "r"(a[0]), "r"(a[1]), "r"(a[2]), "r"(a[3]), "r"(b0), "r"(b1));
}
__device__ __forceinline__ void mma16816h(float (&c)[4], const uint32_t (&a)[4],
                                          uint32_t b0, uint32_t b1) {
    asm volatile(
        "mma.sync.aligned.m16n8k16.row.col.f32.f16.f16.f32 "
        "{%0,%1,%2,%3}, {%4,%5,%6,%7}, {%8,%9}, {%0,%1,%2,%3};"
        : "+f"(c[0]), "+f"(c[1]), "+f"(c[2]), "+f"(c[3])
        : "r"(a[0]), "r"(a[1]), "r"(a[2]), "r"(a[3]), "r"(b0), "r"(b1));
}

// Fast exp on the FMA/ALU pipes (no MUFU). rel err ~3e-6. Handles -1e30 -> ~0.
__device__ __forceinline__ float fexp(float x) {
    float y = x * 1.4426950408889634f;
    y = fmaxf(y, -126.0f);
    float r = y + 12582912.0f;
    float n = r - 12582912.0f;
    float f = y - n;
    int   e = __float_as_int(r);
    float u = f * 0.6931471805599453f;
    float p = 8.3333333e-3f;
    p = fmaf(p, u, 4.1666667e-2f);
    p = fmaf(p, u, 1.6666667e-1f);
    p = fmaf(p, u, 5.0e-1f);
    p = fmaf(p, u, 1.0f);
    p = fmaf(p, u, 1.0f);
    int sc = (e - 0x4B400000 + 127) << 23;
    return __int_as_float(sc) * p;
}

__device__ __forceinline__ void split_pack(float a, float b,
                                           uint32_t& hi, uint32_t& lo) {
    __nv_bfloat16 ha = __float2bfloat16(a);
    __nv_bfloat16 hb = __float2bfloat16(b);
    __nv_bfloat16 la = __float2bfloat16(a - __bfloat162float(ha));
    __nv_bfloat16 lb = __float2bfloat16(b - __bfloat162float(hb));
    __nv_bfloat162 H(ha, hb), L(la, lb);
    hi = *reinterpret_cast<uint32_t*>(&H);
    lo = *reinterpret_cast<uint32_t*>(&L);
}
__device__ __forceinline__ uint32_t pack_h2(float a, float b) {
    __half2 h(__float2half(a), __float2half(b));
    return *reinterpret_cast<uint32_t*>(&h);
}

// ---------------------------------------------------------------------------
// x fp32 -> fp16
// ---------------------------------------------------------------------------
__global__ void x_to_f16(const float* __restrict__ x)
{
    int i = blockIdx.x * blockDim.x + threadIdx.x;
    if (i >= Mrows * Cn / 4) return;
    float4 v = ((const float4*)x)[i];
    *(uint32_t*)(g_x16 + (size_t)i*4)     = pack_h2(v.x, v.y);
    *(uint32_t*)(g_x16 + (size_t)i*4 + 2) = pack_h2(v.z, v.w);
}

// ---------------------------------------------------------------------------
// QKV weights: [H][C][D] fp32 -> g_wt16 [sel][H*D][C] fp16 (transposed)
// ---------------------------------------------------------------------------
__global__ void transpose_w_f16(const float* __restrict__ in, int sel)
{
    __shared__ float t[32][33];
    const int z = blockIdx.z;
    const float* src = in + (size_t)z * Cn * Dn;
    __half* dst = g_wt16 + (size_t)sel * Cn * Cn + (size_t)z * Dn * Cn;
    const int c0 = blockIdx.x * 32, r0 = blockIdx.y * 32;
    const int tx = threadIdx.x, ty = threadIdx.y;
    #pragma unroll
    for (int j = 0; j < 4; j++)
        t[ty + 8*j][tx] = src[(size_t)(r0 + ty + 8*j) * Dn + c0 + tx];
    __syncthreads();
    #pragma unroll
    for (int j = 0; j < 4; j++)
        dst[(size_t)(c0 + ty + 8*j) * Cn + r0 + tx] = __float2half(t[tx][ty + 8*j]);
}

// ---------------------------------------------------------------------------
// w_proj [C][C] fp32 -> g_wp16 [N][K] fp16 (transposed)
// ---------------------------------------------------------------------------
__global__ void transpose_wproj(const float* __restrict__ in)
{
    __shared__ float t[32][33];
    const int c0 = blockIdx.x * 32, r0 = blockIdx.y * 32;
    const int tx = threadIdx.x, ty = threadIdx.y;
    #pragma unroll
    for (int j = 0; j < 4; j++)
        t[ty + 8*j][tx] = in[(size_t)(r0 + ty + 8*j) * Cn + c0 + tx];
    __syncthreads();
    #pragma unroll
    for (int j = 0; j < 4; j++)
        g_wp16[(size_t)(c0 + ty + 8*j) * Cn + r0 + tx] = __float2half(t[tx][ty + 8*j]);
}

// ---------------------------------------------------------------------------
// V transpose+split: g_v [BH][T][D] fp32 -> g_vthi/lo [BH][D][T] bf16
// ---------------------------------------------------------------------------
__global__ void v_transpose_split()
{
    __shared__ float t[32][33];
    const int z = blockIdx.z;
    const int t0 = blockIdx.x * 32, d0 = blockIdx.y * 32;
    const float* src = g_v + (size_t)z * Tn * Dn;
    __nv_bfloat16* dhi = g_vthi + (size_t)z * Dn * Tn;
    __nv_bfloat16* dlo = g_vtlo + (size_t)z * Dn * Tn;
    const int tx = threadIdx.x, ty = threadIdx.y;
    #pragma unroll
    for (int j = 0; j < 4; j++)
        t[ty + 8*j][tx] = src[(size_t)(t0 + ty + 8*j) * Dn + d0 + tx];
    __syncthreads();
    #pragma unroll
    for (int j = 0; j < 4; j++) {
        float a = t[tx][ty + 8*j];
        __nv_bfloat16 h = __float2bfloat16(a);
        size_t o = (size_t)(d0 + ty + 8*j) * Tn + t0 + tx;
        dhi[o] = h;
        dlo[o] = __float2bfloat16(a - __bfloat162float(h));
    }
}

// ---------------------------------------------------------------------------
// Shared GEMM geometry
// ---------------------------------------------------------------------------
#define KPITCH 40
#define ROWB   (KPITCH*2)         // 80 B
#define TILEB  (128*ROWB)         // 10240 B
#define NCHUNK (Cn/32)            // 32
#define STAGE2 (2*TILEB)          // A + B
#define GSMEM2 (2*STAGE2)         // 40960

// ---------------------------------------------------------------------------
// fp16 single-pass GEMM: C[8192,1024] = A * B^T (B stored [N][K])
// mode 0 (QKV, z=blockIdx.z): z=0 q->fp16 scaled, z=1 k->fp16, z=2 v->fp32
// mode 1 (proj): +bias -> outp fp32
// ---------------------------------------------------------------------------
__device__ __forceinline__ void load_chunk2(uint32_t sbase,
    const __half* __restrict__ Ag, const __half* __restrict__ Bg,
    int k0, int tid)
{
    const __half* gsrc[2] = {Ag, Bg};
    #pragma unroll
    for (int a = 0; a < 2; a++) {
        #pragma unroll
        for (int j = 0; j < 2; j++) {
            int o = tid + j * 256;
            int row = o >> 2, ch = o & 3;
            cp16(sbase + a * TILEB + row * ROWB + ch * 16,
                 gsrc[a] + (size_t)row * Cn + k0 + ch * 8);
        }
    }
}

__global__ __launch_bounds__(256) void gemm_f16(
    const float* __restrict__ bias, float* __restrict__ outp, int mode)
{
    extern __shared__ __align__(128) char smem[];
    const uint32_t smem_base = smem_to_u32(smem);
    const int tid = threadIdx.x;
    const int lane = tid & 31, wid = tid >> 5;
    const int wm = wid >> 2, wn = wid & 3;
    const int nb = blockIdx.x, mt = blockIdx.y, z = blockIdx.z;

    const __half* Ag = (mode == 0 ? g_x16 : g_att16) + (size_t)mt * 128 * Cn;
    const __half* Bg = (mode == 0 ? g_wt16 + (size_t)z * Cn * Cn : g_wp16)
                       + (size_t)nb * 128 * Cn;

    float acc[4][4][4] = {};
    const uint32_t a_row  = (lane & 15);
    const uint32_t a_kb   = (lane >> 4) << 4;
    const uint32_t b_noff = ((lane >> 4) << 3) + (lane & 7);
    const uint32_t b_kb   = ((lane >> 3) & 1) << 4;

    load_chunk2(smem_base, Ag, Bg, 0, tid);
    cp_commit();

    for (int i = 0; i < NCHUNK; i++) {
        const int buf = i & 1;
        if (i + 1 < NCHUNK) {
            load_chunk2(smem_base + (buf ^ 1) * STAGE2, Ag, Bg, (i + 1) * 32, tid);
            cp_commit();
            asm volatile("cp.async.wait_group 1;" ::: "memory");
        } else {
            asm volatile("cp.async.wait_group 0;" ::: "memory");
        }
        __syncthreads();

        const uint32_t sb = smem_base + buf * STAGE2;
        #pragma unroll
        for (int ks = 0; ks < 2; ks++) {
            uint32_t bb[2][4];
            #pragma unroll
            for (int p = 0; p < 2; p++) {
                uint32_t n = wn * 32 + p * 16 + b_noff;
                ldsm4(bb[p], sb + TILEB + n * ROWB + ks * 32 + b_kb);
            }
            #pragma unroll
            for (int mi = 0; mi < 4; mi++) {
                uint32_t r = wm * 64 + mi * 16 + a_row;
                uint32_t aa[4];
                ldsm4(aa, sb + r * ROWB + ks * 32 + a_kb);
                #pragma unroll
                for (int j = 0; j < 4; j++)
                    mma16816h(acc[mi][j], aa,
                              bb[j >> 1][(j & 1) * 2], bb[j >> 1][(j & 1) * 2 + 1]);
            }
        }
        __syncthreads();
    }

    const int lr = lane >> 2;
    const int lc = (lane & 3) * 2;
    #pragma unroll
    for (int mi = 0; mi < 4; mi++) {
        #pragma unroll
        for (int j = 0; j < 4; j++) {
            int row = mt * 128 + wm * 64 + mi * 16 + lr;
            int col = nb * 128 + wn * 32 + j * 8 + lc;
            if (mode == 1) {
                float2 bv = *(const float2*)(bias + col);
                *(float2*)(outp + (size_t)row * Cn + col) =
                    make_float2(acc[mi][j][0] + bv.x, acc[mi][j][1] + bv.y);
                *(float2*)(outp + (size_t)(row + 8) * Cn + col) =
                    make_float2(acc[mi][j][2] + bv.x, acc[mi][j][3] + bv.y);
            } else {
                int b = row >> 11, t = row & 2047;
                int h = col >> 6, d = col & 63;
                size_t off = ((size_t)((b << 4) + h) * Tn + t) * Dn + d;
                if (z == 2) {
                    *(float2*)(g_v + off) = make_float2(acc[mi][j][0], acc[mi][j][1]);
                    *(float2*)(g_v + off + 8 * Dn) = make_float2(acc[mi][j][2], acc[mi][j][3]);
                } else {
                    const float sc = (z == 0) ? 0.03125f : 1.0f;
                    __half* dst = (z == 0) ? g_q16 : g_k16;
                    *(uint32_t*)(dst + off) =
                        pack_h2(acc[mi][j][0] * sc, acc[mi][j][1] * sc);
                    *(uint32_t*)(dst + off + 8 * Dn) =
                        pack_h2(acc[mi][j][2] * sc, acc[mi][j][3] * sc);
                }
            }
        }
    }
}

// ---------------------------------------------------------------------------
// HMMA flash attention: fp16 QK (1 MMA/term), bf16x3 PV, FMA-pipe exp.
// Epilogue writes att directly as fp16 [B][T][H*D].
// ---------------------------------------------------------------------------
#define AT_PITCH 144
#define AT_TILE  (64*AT_PITCH)       // 9216
#define AT_STAGE (3*AT_TILE)         // 27648: Kf, Vh, Vl
#define AT_SMEM  (2*AT_STAGE)        // 55296

__device__ __forceinline__ void at_load_kv(uint32_t dstbase,
    const __half* __restrict__ Kf,
    const __nv_bfloat16* __restrict__ Vth, const __nv_bfloat16* __restrict__ Vtl,
    int jt, int tid)
{
    const int koff = jt * 64;
    #pragma unroll
    for (int i = 0; i < 6; i++) {
        int c = tid + i * 256;           // 0..1535
        int arr = c >> 9;                // 0..2
        int cc = c & 511;
        int row = cc >> 3, o = cc & 7;
        const void* g;
        if (arr == 0)      g = Kf  + (size_t)(koff + row) * Dn + o * 8;
        else if (arr == 1) g = Vth + (size_t)row * Tn + koff + o * 8;
        else               g = Vtl + (size_t)row * Tn + koff + o * 8;
        cp16(dstbase + arr * AT_TILE + row * AT_PITCH + o * 16, g);
    }
}

__global__ __launch_bounds__(256, 1) void attn_mma()
{
    extern __shared__ __align__(128) char smem[];
    const uint32_t sb = smem_to_u32(smem);
    const int tid = threadIdx.x;
    const int lane = tid & 31, wid = tid >> 5;
    const int qt = blockIdx.x, bh = blockIdx.y;
    const int b = bh >> 4, h = bh & 15;

    const __half* Qf = g_q16 + ((size_t)bh * Tn + qt * 128) * Dn;
    const __half* Kf = g_k16 + (size_t)bh * Tn * Dn;
    const __nv_bfloat16* Vth = g_vthi + (size_t)bh * Dn * Tn;
    const __nv_bfloat16* Vtl = g_vtlo + (size_t)bh * Dn * Tn;

    // stage Q (128 x 64 fp16) into smem, then ldmatrix to registers
    #pragma unroll
    for (int i = 0; i < 4; i++) {
        int c = tid + i * 256;           // 0..1023
        int row = c >> 3, o = c & 7;
        cp16(sb + row * AT_PITCH + o * 16, Qf + (size_t)row * Dn + o * 8);
    }
    cp_commit();
    asm volatile("cp.async.wait_group 0;" ::: "memory");
    __syncthreads();

    uint32_t qf[4][4];
    {
        uint32_t abase = sb + (wid * 16 + (lane & 15)) * AT_PITCH + ((lane >> 4) << 4);
        #pragma unroll
        for (int kk = 0; kk < 4; kk++)
            ldsm4(qf[kk], abase + kk * 32);
    }
    __syncthreads();

    const uint32_t b_noff = ((lane >> 4) << 3) + (lane & 7);
    const uint32_t b_kb   = ((lane >> 3) & 1) << 4;

    float o_[8][4] = {};
    float m0 = -1e30f, m1 = -1e30f, l0 = 0.0f, l1 = 0.0f;

    const int jmax = 2 * qt + 1;
    at_load_kv(sb, Kf, Vth, Vtl, 0, tid);
    cp_commit();

    for (int jt = 0; jt <= jmax; jt++) {
        const int stg = jt & 1;
        if (jt < jmax) {
            at_load_kv(sb + (stg ^ 1) * AT_STAGE, Kf, Vth, Vtl, jt + 1, tid);
            cp_commit();
            asm volatile("cp.async.wait_group 1;" ::: "memory");
        } else {
            asm volatile("cp.async.wait_group 0;" ::: "memory");
        }
        __syncthreads();

        const uint32_t s0 = sb + stg * AT_STAGE;

        // ---- S = Q @ K^T (fp16 single-pass) ----
        float s[8][4];
        #pragma unroll
        for (int j = 0; j < 8; j++)
            #pragma unroll
            for (int c = 0; c < 4; c++) s[j][c] = 0.0f;

        #pragma unroll
        for (int j = 0; j < 4; j++) {
            #pragma unroll
            for (int kk = 0; kk < 4; kk++) {
                uint32_t kf4[4];
                ldsm4(kf4, s0 + (j * 16 + b_noff) * AT_PITCH + kk * 32 + b_kb);
                mma16816h(s[2*j],   qf[kk], kf4[0], kf4[1]);
                mma16816h(s[2*j+1], qf[kk], kf4[2], kf4[3]);
            }
        }

        // ---- causal mask ----
        const int r0 = qt * 128 + wid * 16 + (lane >> 2);
        const int r1 = r0 + 8;
        if (jt >= 2 * qt) {
            #pragma unroll
            for (int j = 0; j < 8; j++) {
                int kc = jt * 64 + j * 8 + 2 * (lane & 3);
                if (kc     > r0) s[j][0] = -1e30f;
                if (kc + 1 > r0) s[j][1] = -1e30f;
                if (kc     > r1) s[j][2] = -1e30f;
                if (kc + 1 > r1) s[j][3] = -1e30f;
            }
        }

        // ---- online softmax ----
        float mt0 = -1e30f, mt1 = -1e30f;
        #pragma unroll
        for (int j = 0; j < 8; j++) {
            mt0 = fmaxf(mt0, fmaxf(s[j][0], s[j][1]));
            mt1 = fmaxf(mt1, fmaxf(s[j][2], s[j][3]));
        }
        mt0 = fmaxf(mt0, __shfl_xor_sync(0xffffffffu, mt0, 1));
        mt0 = fmaxf(mt0, __shfl_xor_sync(0xffffffffu, mt0, 2));
        mt1 = fmaxf(mt1, __shfl_xor_sync(0xffffffffu, mt1, 1));
        mt1 = fmaxf(mt1, __shfl_xor_sync(0xffffffffu, mt1, 2));

        float mn0 = fmaxf(m0, mt0), mn1 = fmaxf(m1, mt1);
        float al0 = fexp(m0 - mn0), al1 = fexp(m1 - mn1);
        m0 = mn0; m1 = mn1;
        l0 *= al0; l1 *= al1;
        #pragma unroll
        for (int j = 0; j < 8; j++) {
            o_[j][0] *= al0; o_[j][1] *= al0;
            o_[j][2] *= al1; o_[j][3] *= al1;
        }
        float rs0 = 0.0f, rs1 = 0.0f;
        #pragma unroll
        for (int j = 0; j < 8; j++) {
            s[j][0] = fexp(s[j][0] - mn0); rs0 += s[j][0];
            s[j][1] = fexp(s[j][1] - mn0); rs0 += s[j][1];
            s[j][2] = fexp(s[j][2] - mn1); rs1 += s[j][2];
            s[j][3] = fexp(s[j][3] - mn1); rs1 += s[j][3];
        }
        rs0 += __shfl_xor_sync(0xffffffffu, rs0, 1);
        rs0 += __shfl_xor_sync(0xffffffffu, rs0, 2);
        rs1 += __shfl_xor_sync(0xffffffffu, rs1, 1);
        rs1 += __shfl_xor_sync(0xffffffffu, rs1, 2);
        l0 += rs0; l1 += rs1;

        // ---- pack P hi/lo bf16 ----
        uint32_t ph[4][4], pl[4][4];
        #pragma unroll
        for (int kk = 0; kk < 4; kk++) {
            split_pack(s[2*kk][0],   s[2*kk][1],   ph[kk][0], pl[kk][0]);
            split_pack(s[2*kk][2],   s[2*kk][3],   ph[kk][1], pl[kk][1]);
            split_pack(s[2*kk+1][0], s[2*kk+1][1], ph[kk][2], pl[kk][2]);
            split_pack(s[2*kk+1][2], s[2*kk+1][3], ph[kk][3], pl[kk][3]);
        }

        // ---- O += P @ V (bf16x3) ----
        #pragma unroll
        for (int jd = 0; jd < 4; jd++) {
            #pragma unroll
            for (int kk = 0; kk < 4; kk++) {
                uint32_t vh4[4], vl4[4];
                uint32_t addr = s0 + AT_TILE + (jd * 16 + b_noff) * AT_PITCH
                                + kk * 32 + b_kb;
                ldsm4(vh4, addr);
                ldsm4(vl4, addr + AT_TILE);
                mma16816(o_[2*jd],   ph[kk], vh4[0], vh4[1]);
                mma16816(o_[2*jd],   ph[kk], vl4[0], vl4[1]);
                mma16816(o_[2*jd],   pl[kk], vh4[0], vh4[1]);
                mma16816(o_[2*jd+1], ph[kk], vh4[2], vh4[3]);
                mma16816(o_[2*jd+1], ph[kk], vl4[2], vl4[3]);
                mma16816(o_[2*jd+1], pl[kk], vh4[2], vh4[3]);
            }
        }
        __syncthreads();
    }

    // epilogue: normalize + write att fp16 [B][T][H*D]
    const float inv0 = 1.0f / l0, inv1 = 1.0f / l1;
    const int r0 = qt * 128 + wid * 16 + (lane >> 2);
    size_t off = ((size_t)b * Tn + r0) * Cn + h * 64;
    #pragma unroll
    for (int j = 0; j < 8; j++) {
        int d = j * 8 + 2 * (lane & 3);
        *(uint32_t*)(g_att16 + off + d) = pack_h2(o_[j][0] * inv0, o_[j][1] * inv0);
        *(uint32_t*)(g_att16 + off + 8 * Cn + d) = pack_h2(o_[j][2] * inv1, o_[j][3] * inv1);
    }
}

// ---------------------------------------------------------------------------
extern "C" void kernel_launch(void* const* d_in, const int* in_sizes, int n_in,
                              void* d_out, int out_size)
{
    const float* x      = (const float*)d_in[0];
    const float* wq     = (const float*)d_in[1];
    const float* wk     = (const float*)d_in[2];
    const float* wv     = (const float*)d_in[3];
    const float* w_proj = (const float*)d_in[4];
    const float* b_proj = (const float*)d_in[5];
    float* out = (float*)d_out;

    cudaFuncSetAttribute(attn_mma,
                         cudaFuncAttributeMaxDynamicSharedMemorySize, AT_SMEM);

    // 1) x -> fp16
    int n4 = Mrows * Cn / 4;
    x_to_f16<<<(n4 + 255) / 256, 256>>>(x);

    // 2) weights -> fp16 transposed
    transpose_w_f16<<<dim3(Dn/32, Cn/32, Hn), dim3(32,8)>>>(wq, 0);
    transpose_w_f16<<<dim3(Dn/32, Cn/32, Hn), dim3(32,8)>>>(wk, 1);
    transpose_w_f16<<<dim3(Dn/32, Cn/32, Hn), dim3(32,8)>>>(wv, 2);
    transpose_wproj<<<dim3(Cn/32, Cn/32), dim3(32,8)>>>(w_proj);

    // 3) QKV GEMM (fp16 single-pass; q/k -> fp16, v -> fp32)
    gemm_f16<<<dim3(Cn/128, Mrows/128, 3), 256, GSMEM2>>>(nullptr, nullptr, 0);

    // 4) V transpose+split (bf16 hi/lo)
    v_transpose_split<<<dim3(Tn/32, Dn/32, Bn*Hn), dim3(32,8)>>>();

    // 5) attention (fp16 QK + bf16x3 PV); writes att fp16
    attn_mma<<<dim3(Tn/128, Bn*Hn), 256, AT_SMEM>>>();

    // 6) output projection (fp16 single-pass, +bias)
    gemm_f16<<<dim3(Cn/128, Mrows/128, 1), 256, GSMEM2>>>(b_proj, out, 1);
}

// round 8
// speedup vs baseline: 5.0238x; 1.1814x over previous
#include <cuda_runtime.h>
#include <cuda_bf16.h>
#include <cuda_fp16.h>
#include <cstdint>

// Problem constants
#define Bn 4
#define Tn 2048
#define Cn 1024
#define Hn 16
#define Dn 64
#define Mrows (Bn*Tn)   // 8192

// ---------------------------------------------------------------------------
// Scratch (allocation-free rule: __device__ globals), 16B-aligned
// ---------------------------------------------------------------------------
__device__ __align__(16) float g_v[Bn*Hn*Tn*Dn];        // [B*H][T][D] fp32

__device__ __align__(16) __half g_q16[Bn*Hn*Tn*Dn];     // [B*H][T][D], pre-scaled
__device__ __align__(16) __half g_k16[Bn*Hn*Tn*Dn];
__device__ __align__(16) __half g_vt16[Bn*Hn*Dn*Tn];    // [B*H][D][T] (V^T) fp16

__device__ __align__(16) __half g_x16[Mrows*Cn];        // x as fp16
__device__ __align__(16) __half g_wt16[3*Cn*Cn];        // qkv weights [3][N][K] fp16
__device__ __align__(16) __half g_wp16[Cn*Cn];          // w_proj^T [N][K] fp16
__device__ __align__(16) __half g_att16[Mrows*Cn];      // attention out [B][T][H*D] fp16

// ---------------------------------------------------------------------------
// PTX helpers (sm_100-portable)
// ---------------------------------------------------------------------------
__device__ __forceinline__ uint32_t smem_to_u32(const void* p) {
    uint32_t a;
    asm("{ .reg .u64 t; cvta.to.shared.u64 t, %1; cvt.u32.u64 %0, t; }"
        : "=r"(a) : "l"(p));
    return a;
}
__device__ __forceinline__ void cp16(uint32_t dst, const void* src) {
    asm volatile("cp.async.cg.shared.global [%0], [%1], 16;"
                 :: "r"(dst), "l"(src) : "memory");
}
__device__ __forceinline__ void cp_commit() {
    asm volatile("cp.async.commit_group;" ::: "memory");
}
__device__ __forceinline__ void ldsm4(uint32_t (&r)[4], uint32_t addr) {
    asm volatile("ldmatrix.sync.aligned.m8n8.x4.shared.b16 {%0,%1,%2,%3}, [%4];"
                 : "=r"(r[0]), "=r"(r[1]), "=r"(r[2]), "=r"(r[3]) : "r"(addr));
}
__device__ __forceinline__ void mma16816h(float (&c)[4], const uint32_t (&a)[4],
                                          uint32_t b0, uint32_t b1) {
    asm volatile(
        "mma.sync.aligned.m16n8k16.row.col.f32.f16.f16.f32 "
        "{%0,%1,%2,%3}, {%4,%5,%6,%7}, {%8,%9}, {%0,%1,%2,%3};"
        : "+f"(c[0]), "+f"(c[1]), "+f"(c[2]), "+f"(c[3])
        : "r"(a[0]), "r"(a[1]), "r"(a[2]), "r"(a[3]), "r"(b0), "r"(b1));
}

// Fast exp on the FMA/ALU pipes (no MUFU), degree-4, abs err ~4e-5 near P<=1.
__device__ __forceinline__ float fexp(float x) {
    float y = x * 1.4426950408889634f;
    y = fmaxf(y, -126.0f);
    float r = y + 12582912.0f;
    float n = r - 12582912.0f;
    float f = y - n;
    int   e = __float_as_int(r);
    float u = f * 0.6931471805599453f;
    float p = 4.1666667e-2f;             // 1/24
    p = fmaf(p, u, 1.6666667e-1f);
    p = fmaf(p, u, 5.0e-1f);
    p = fmaf(p, u, 1.0f);
    p = fmaf(p, u, 1.0f);
    int sc = (e - 0x4B400000 + 127) << 23;
    return __int_as_float(sc) * p;
}

__device__ __forceinline__ uint32_t pack_h2(float a, float b) {
    __half2 h(__float2half(a), __float2half(b));
    return *reinterpret_cast<uint32_t*>(&h);
}

// ---------------------------------------------------------------------------
// x fp32 -> fp16
// ---------------------------------------------------------------------------
__global__ void x_to_f16(const float* __restrict__ x)
{
    int i = blockIdx.x * blockDim.x + threadIdx.x;
    if (i >= Mrows * Cn / 4) return;
    float4 v = ((const float4*)x)[i];
    *(uint32_t*)(g_x16 + (size_t)i*4)     = pack_h2(v.x, v.y);
    *(uint32_t*)(g_x16 + (size_t)i*4 + 2) = pack_h2(v.z, v.w);
}

// ---------------------------------------------------------------------------
// QKV weights (all 3 in one launch): [H][C][D] fp32 -> g_wt16 [sel][H*D][C]
// Grid (Dn/32, Cn/32, 3*Hn), block (32,8). z: sel = z/16, head = z%16.
// ---------------------------------------------------------------------------
__global__ void transpose_w_f16(const float* __restrict__ wq,
                                const float* __restrict__ wk,
                                const float* __restrict__ wv)
{
    __shared__ float t[32][33];
    const int sel = blockIdx.z >> 4;
    const int z   = blockIdx.z & 15;
    const float* w = (sel == 0 ? wq : (sel == 1 ? wk : wv));
    const float* src = w + (size_t)z * Cn * Dn;
    __half* dst = g_wt16 + (size_t)sel * Cn * Cn + (size_t)z * Dn * Cn;
    const int c0 = blockIdx.x * 32, r0 = blockIdx.y * 32;
    const int tx = threadIdx.x, ty = threadIdx.y;
    #pragma unroll
    for (int j = 0; j < 4; j++)
        t[ty + 8*j][tx] = src[(size_t)(r0 + ty + 8*j) * Dn + c0 + tx];
    __syncthreads();
    #pragma unroll
    for (int j = 0; j < 4; j++)
        dst[(size_t)(c0 + ty + 8*j) * Cn + r0 + tx] = __float2half(t[tx][ty + 8*j]);
}

// ---------------------------------------------------------------------------
// w_proj [C][C] fp32 -> g_wp16 [N][K] fp16 (transposed)
// ---------------------------------------------------------------------------
__global__ void transpose_wproj(const float* __restrict__ in)
{
    __shared__ float t[32][33];
    const int c0 = blockIdx.x * 32, r0 = blockIdx.y * 32;
    const int tx = threadIdx.x, ty = threadIdx.y;
    #pragma unroll
    for (int j = 0; j < 4; j++)
        t[ty + 8*j][tx] = in[(size_t)(r0 + ty + 8*j) * Cn + c0 + tx];
    __syncthreads();
    #pragma unroll
    for (int j = 0; j < 4; j++)
        g_wp16[(size_t)(c0 + ty + 8*j) * Cn + r0 + tx] = __float2half(t[tx][ty + 8*j]);
}

// ---------------------------------------------------------------------------
// V transpose: g_v [BH][T][D] fp32 -> g_vt16 [BH][D][T] fp16
// ---------------------------------------------------------------------------
__global__ void v_transpose_f16()
{
    __shared__ float t[32][33];
    const int z = blockIdx.z;
    const int t0 = blockIdx.x * 32, d0 = blockIdx.y * 32;
    const float* src = g_v + (size_t)z * Tn * Dn;
    __half* dst = g_vt16 + (size_t)z * Dn * Tn;
    const int tx = threadIdx.x, ty = threadIdx.y;
    #pragma unroll
    for (int j = 0; j < 4; j++)
        t[ty + 8*j][tx] = src[(size_t)(t0 + ty + 8*j) * Dn + d0 + tx];
    __syncthreads();
    #pragma unroll
    for (int j = 0; j < 4; j++)
        dst[(size_t)(d0 + ty + 8*j) * Tn + t0 + tx] = __float2half(t[tx][ty + 8*j]);
}

// ---------------------------------------------------------------------------
// Shared GEMM geometry
// ---------------------------------------------------------------------------
#define KPITCH 40
#define ROWB   (KPITCH*2)         // 80 B
#define TILEB  (128*ROWB)         // 10240 B
#define NCHUNK (Cn/32)            // 32
#define STAGE2 (2*TILEB)          // A + B
#define GSMEM2 (2*STAGE2)         // 40960

// ---------------------------------------------------------------------------
// fp16 single-pass GEMM: C[8192,1024] = A * B^T (B stored [N][K])
// mode 0 (QKV, z=blockIdx.z): z=0 q->fp16 scaled, z=1 k->fp16, z=2 v->fp32
// mode 1 (proj): +bias -> outp fp32
// ---------------------------------------------------------------------------
__device__ __forceinline__ void load_chunk2(uint32_t sbase,
    const __half* __restrict__ Ag, const __half* __restrict__ Bg,
    int k0, int tid)
{
    const __half* gsrc[2] = {Ag, Bg};
    #pragma unroll
    for (int a = 0; a < 2; a++) {
        #pragma unroll
        for (int j = 0; j < 2; j++) {
            int o = tid + j * 256;
            int row = o >> 2, ch = o & 3;
            cp16(sbase + a * TILEB + row * ROWB + ch * 16,
                 gsrc[a] + (size_t)row * Cn + k0 + ch * 8);
        }
    }
}

__global__ __launch_bounds__(256) void gemm_f16(
    const float* __restrict__ bias, float* __restrict__ outp, int mode)
{
    extern __shared__ __align__(128) char smem[];
    const uint32_t smem_base = smem_to_u32(smem);
    const int tid = threadIdx.x;
    const int lane = tid & 31, wid = tid >> 5;
    const int wm = wid >> 2, wn = wid & 3;
    const int nb = blockIdx.x, mt = blockIdx.y, z = blockIdx.z;

    const __half* Ag = (mode == 0 ? g_x16 : g_att16) + (size_t)mt * 128 * Cn;
    const __half* Bg = (mode == 0 ? g_wt16 + (size_t)z * Cn * Cn : g_wp16)
                       + (size_t)nb * 128 * Cn;

    float acc[4][4][4] = {};
    const uint32_t a_row  = (lane & 15);
    const uint32_t a_kb   = (lane >> 4) << 4;
    const uint32_t b_noff = ((lane >> 4) << 3) + (lane & 7);
    const uint32_t b_kb   = ((lane >> 3) & 1) << 4;

    load_chunk2(smem_base, Ag, Bg, 0, tid);
    cp_commit();

    for (int i = 0; i < NCHUNK; i++) {
        const int buf = i & 1;
        if (i + 1 < NCHUNK) {
            load_chunk2(smem_base + (buf ^ 1) * STAGE2, Ag, Bg, (i + 1) * 32, tid);
            cp_commit();
            asm volatile("cp.async.wait_group 1;" ::: "memory");
        } else {
            asm volatile("cp.async.wait_group 0;" ::: "memory");
        }
        __syncthreads();

        const uint32_t sb = smem_base + buf * STAGE2;
        #pragma unroll
        for (int ks = 0; ks < 2; ks++) {
            uint32_t bb[2][4];
            #pragma unroll
            for (int p = 0; p < 2; p++) {
                uint32_t n = wn * 32 + p * 16 + b_noff;
                ldsm4(bb[p], sb + TILEB + n * ROWB + ks * 32 + b_kb);
            }
            #pragma unroll
            for (int mi = 0; mi < 4; mi++) {
                uint32_t r = wm * 64 + mi * 16 + a_row;
                uint32_t aa[4];
                ldsm4(aa, sb + r * ROWB + ks * 32 + a_kb);
                #pragma unroll
                for (int j = 0; j < 4; j++)
                    mma16816h(acc[mi][j], aa,
                              bb[j >> 1][(j & 1) * 2], bb[j >> 1][(j & 1) * 2 + 1]);
            }
        }
        __syncthreads();
    }

    const int lr = lane >> 2;
    const int lc = (lane & 3) * 2;
    #pragma unroll
    for (int mi = 0; mi < 4; mi++) {
        #pragma unroll
        for (int j = 0; j < 4; j++) {
            int row = mt * 128 + wm * 64 + mi * 16 + lr;
            int col = nb * 128 + wn * 32 + j * 8 + lc;
            if (mode == 1) {
                float2 bv = *(const float2*)(bias + col);
                *(float2*)(outp + (size_t)row * Cn + col) =
                    make_float2(acc[mi][j][0] + bv.x, acc[mi][j][1] + bv.y);
                *(float2*)(outp + (size_t)(row + 8) * Cn + col) =
                    make_float2(acc[mi][j][2] + bv.x, acc[mi][j][3] + bv.y);
            } else {
                int b = row >> 11, t = row & 2047;
                int h = col >> 6, d = col & 63;
                size_t off = ((size_t)((b << 4) + h) * Tn + t) * Dn + d;
                if (z == 2) {
                    *(float2*)(g_v + off) = make_float2(acc[mi][j][0], acc[mi][j][1]);
                    *(float2*)(g_v + off + 8 * Dn) = make_float2(acc[mi][j][2], acc[mi][j][3]);
                } else {
                    const float sc = (z == 0) ? 0.03125f : 1.0f;
                    __half* dst = (z == 0) ? g_q16 : g_k16;
                    *(uint32_t*)(dst + off) =
                        pack_h2(acc[mi][j][0] * sc, acc[mi][j][1] * sc);
                    *(uint32_t*)(dst + off + 8 * Dn) =
                        pack_h2(acc[mi][j][2] * sc, acc[mi][j][3] * sc);
                }
            }
        }
    }
}

// ---------------------------------------------------------------------------
// HMMA flash attention: fp16 QK, fp16 PV (single-pass), FMA-pipe exp.
// Grid (T/128, B*H), 256 threads = 8 warps (16 query rows each), 64-key tiles.
// ---------------------------------------------------------------------------
#define AT_PITCH 144
#define AT_TILE  (64*AT_PITCH)       // 9216
#define AT_STAGE (2*AT_TILE)         // 18432: Kf, Vf
#define AT_SMEM  (2*AT_STAGE)        // 36864

__device__ __forceinline__ void at_load_kv(uint32_t dstbase,
    const __half* __restrict__ Kf, const __half* __restrict__ Vtf,
    int jt, int tid)
{
    const int koff = jt * 64;
    #pragma unroll
    for (int i = 0; i < 4; i++) {
        int c = tid + i * 256;           // 0..1023
        int arr = c >> 9;                // 0..1
        int cc = c & 511;
        int row = cc >> 3, o = cc & 7;
        const void* g = arr ? (const void*)(Vtf + (size_t)row * Tn + koff + o * 8)
                            : (const void*)(Kf + (size_t)(koff + row) * Dn + o * 8);
        cp16(dstbase + arr * AT_TILE + row * AT_PITCH + o * 16, g);
    }
}

__global__ __launch_bounds__(256, 1) void attn_mma()
{
    extern __shared__ __align__(128) char smem[];
    const uint32_t sb = smem_to_u32(smem);
    const int tid = threadIdx.x;
    const int lane = tid & 31, wid = tid >> 5;
    const int qt = blockIdx.x, bh = blockIdx.y;
    const int b = bh >> 4, h = bh & 15;

    const __half* Qf  = g_q16 + ((size_t)bh * Tn + qt * 128) * Dn;
    const __half* Kf  = g_k16 + (size_t)bh * Tn * Dn;
    const __half* Vtf = g_vt16 + (size_t)bh * Dn * Tn;

    // stage Q (128 x 64 fp16) into smem, ldmatrix into registers
    #pragma unroll
    for (int i = 0; i < 4; i++) {
        int c = tid + i * 256;
        int row = c >> 3, o = c & 7;
        cp16(sb + row * AT_PITCH + o * 16, Qf + (size_t)row * Dn + o * 8);
    }
    cp_commit();
    asm volatile("cp.async.wait_group 0;" ::: "memory");
    __syncthreads();

    uint32_t qf[4][4];
    {
        uint32_t abase = sb + (wid * 16 + (lane & 15)) * AT_PITCH + ((lane >> 4) << 4);
        #pragma unroll
        for (int kk = 0; kk < 4; kk++)
            ldsm4(qf[kk], abase + kk * 32);
    }
    __syncthreads();

    const uint32_t b_noff = ((lane >> 4) << 3) + (lane & 7);
    const uint32_t b_kb   = ((lane >> 3) & 1) << 4;

    float o_[8][4] = {};
    float m0 = -1e30f, m1 = -1e30f, l0 = 0.0f, l1 = 0.0f;

    const int jmax = 2 * qt + 1;
    at_load_kv(sb, Kf, Vtf, 0, tid);
    cp_commit();

    for (int jt = 0; jt <= jmax; jt++) {
        const int stg = jt & 1;
        if (jt < jmax) {
            at_load_kv(sb + (stg ^ 1) * AT_STAGE, Kf, Vtf, jt + 1, tid);
            cp_commit();
            asm volatile("cp.async.wait_group 1;" ::: "memory");
        } else {
            asm volatile("cp.async.wait_group 0;" ::: "memory");
        }
        __syncthreads();

        const uint32_t s0 = sb + stg * AT_STAGE;

        // ---- S = Q @ K^T (fp16) ----
        float s[8][4];
        #pragma unroll
        for (int j = 0; j < 8; j++)
            #pragma unroll
            for (int c = 0; c < 4; c++) s[j][c] = 0.0f;

        #pragma unroll
        for (int j = 0; j < 4; j++) {
            #pragma unroll
            for (int kk = 0; kk < 4; kk++) {
                uint32_t kf4[4];
                ldsm4(kf4, s0 + (j * 16 + b_noff) * AT_PITCH + kk * 32 + b_kb);
                mma16816h(s[2*j],   qf[kk], kf4[0], kf4[1]);
                mma16816h(s[2*j+1], qf[kk], kf4[2], kf4[3]);
            }
        }

        // ---- causal mask ----
        const int r0 = qt * 128 + wid * 16 + (lane >> 2);
        const int r1 = r0 + 8;
        if (jt >= 2 * qt) {
            #pragma unroll
            for (int j = 0; j < 8; j++) {
                int kc = jt * 64 + j * 8 + 2 * (lane & 3);
                if (kc     > r0) s[j][0] = -1e30f;
                if (kc + 1 > r0) s[j][1] = -1e30f;
                if (kc     > r1) s[j][2] = -1e30f;
                if (kc + 1 > r1) s[j][3] = -1e30f;
            }
        }

        // ---- online softmax ----
        float mt0 = -1e30f, mt1 = -1e30f;
        #pragma unroll
        for (int j = 0; j < 8; j++) {
            mt0 = fmaxf(mt0, fmaxf(s[j][0], s[j][1]));
            mt1 = fmaxf(mt1, fmaxf(s[j][2], s[j][3]));
        }
        mt0 = fmaxf(mt0, __shfl_xor_sync(0xffffffffu, mt0, 1));
        mt0 = fmaxf(mt0, __shfl_xor_sync(0xffffffffu, mt0, 2));
        mt1 = fmaxf(mt1, __shfl_xor_sync(0xffffffffu, mt1, 1));
        mt1 = fmaxf(mt1, __shfl_xor_sync(0xffffffffu, mt1, 2));

        float mn0 = fmaxf(m0, mt0), mn1 = fmaxf(m1, mt1);
        float al0 = fexp(m0 - mn0), al1 = fexp(m1 - mn1);
        m0 = mn0; m1 = mn1;
        l0 *= al0; l1 *= al1;
        #pragma unroll
        for (int j = 0; j < 8; j++) {
            o_[j][0] *= al0; o_[j][1] *= al0;
            o_[j][2] *= al1; o_[j][3] *= al1;
        }
        float rs0 = 0.0f, rs1 = 0.0f;
        #pragma unroll
        for (int j = 0; j < 8; j++) {
            s[j][0] = fexp(s[j][0] - mn0); rs0 += s[j][0];
            s[j][1] = fexp(s[j][1] - mn0); rs0 += s[j][1];
            s[j][2] = fexp(s[j][2] - mn1); rs1 += s[j][2];
            s[j][3] = fexp(s[j][3] - mn1); rs1 += s[j][3];
        }
        rs0 += __shfl_xor_sync(0xffffffffu, rs0, 1);
        rs0 += __shfl_xor_sync(0xffffffffu, rs0, 2);
        rs1 += __shfl_xor_sync(0xffffffffu, rs1, 1);
        rs1 += __shfl_xor_sync(0xffffffffu, rs1, 2);
        l0 += rs0; l1 += rs1;

        // ---- pack P fp16 A-fragments ----
        uint32_t pf[4][4];
        #pragma unroll
        for (int kk = 0; kk < 4; kk++) {
            pf[kk][0] = pack_h2(s[2*kk][0],   s[2*kk][1]);
            pf[kk][1] = pack_h2(s[2*kk][2],   s[2*kk][3]);
            pf[kk][2] = pack_h2(s[2*kk+1][0], s[2*kk+1][1]);
            pf[kk][3] = pack_h2(s[2*kk+1][2], s[2*kk+1][3]);
        }

        // ---- O += P @ V (fp16 single-pass) ----
        #pragma unroll
        for (int jd = 0; jd < 4; jd++) {
            #pragma unroll
            for (int kk = 0; kk < 4; kk++) {
                uint32_t vf4[4];
                ldsm4(vf4, s0 + AT_TILE + (jd * 16 + b_noff) * AT_PITCH
                           + kk * 32 + b_kb);
                mma16816h(o_[2*jd],   pf[kk], vf4[0], vf4[1]);
                mma16816h(o_[2*jd+1], pf[kk], vf4[2], vf4[3]);
            }
        }
        __syncthreads();
    }

    // epilogue: normalize + write att fp16 [B][T][H*D]
    const float inv0 = 1.0f / l0, inv1 = 1.0f / l1;
    const int r0 = qt * 128 + wid * 16 + (lane >> 2);
    size_t off = ((size_t)b * Tn + r0) * Cn + h * 64;
    #pragma unroll
    for (int j = 0; j < 8; j++) {
        int d = j * 8 + 2 * (lane & 3);
        *(uint32_t*)(g_att16 + off + d) = pack_h2(o_[j][0] * inv0, o_[j][1] * inv0);
        *(uint32_t*)(g_att16 + off + 8 * Cn + d) = pack_h2(o_[j][2] * inv1, o_[j][3] * inv1);
    }
}

// ---------------------------------------------------------------------------
extern "C" void kernel_launch(void* const* d_in, const int* in_sizes, int n_in,
                              void* d_out, int out_size)
{
    const float* x      = (const float*)d_in[0];
    const float* wq     = (const float*)d_in[1];
    const float* wk     = (const float*)d_in[2];
    const float* wv     = (const float*)d_in[3];
    const float* w_proj = (const float*)d_in[4];
    const float* b_proj = (const float*)d_in[5];
    float* out = (float*)d_out;

    // 1) x -> fp16
    int n4 = Mrows * Cn / 4;
    x_to_f16<<<(n4 + 255) / 256, 256>>>(x);

    // 2) weights -> fp16 transposed (qkv merged into one launch)
    transpose_w_f16<<<dim3(Dn/32, Cn/32, 3*Hn), dim3(32,8)>>>(wq, wk, wv);
    transpose_wproj<<<dim3(Cn/32, Cn/32), dim3(32,8)>>>(w_proj);

    // 3) QKV GEMM (fp16 single-pass; q/k -> fp16, v -> fp32)
    gemm_f16<<<dim3(Cn/128, Mrows/128, 3), 256, GSMEM2>>>(nullptr, nullptr, 0);

    // 4) V transpose (fp16)
    v_transpose_f16<<<dim3(Tn/32, Dn/32, Bn*Hn), dim3(32,8)>>>();

    // 5) attention (fp16 QK + fp16 PV)
    attn_mma<<<dim3(Tn/128, Bn*Hn), 256, AT_SMEM>>>();

    // 6) output projection (fp16 single-pass, +bias)
    gemm_f16<<<dim3(Cn/128, Mrows/128, 1), 256, GSMEM2>>>(b_proj, out, 1);
}

// round 9
// speedup vs baseline: 5.3641x; 1.0677x over previous
#include <cuda_runtime.h>
#include <cuda_bf16.h>
#include <cuda_fp16.h>
#include <cstdint>

// Problem constants
#define Bn 4
#define Tn 2048
#define Cn 1024
#define Hn 16
#define Dn 64
#define Mrows (Bn*Tn)   // 8192

// ---------------------------------------------------------------------------
// Scratch (allocation-free rule: __device__ globals), 16B-aligned
// ---------------------------------------------------------------------------
__device__ __align__(16) float g_v[Bn*Hn*Tn*Dn];        // [B*H][T][D] fp32

__device__ __align__(16) __half g_q16[Bn*Hn*Tn*Dn];     // [B*H][T][D], pre-scaled
__device__ __align__(16) __half g_k16[Bn*Hn*Tn*Dn];
__device__ __align__(16) __half g_vt16[Bn*Hn*Dn*Tn];    // [B*H][D][T] (V^T) fp16

__device__ __align__(16) __half g_x16[Mrows*Cn];        // x as fp16
__device__ __align__(16) __half g_wt16[3*Cn*Cn];        // qkv weights [3][N][K] fp16
__device__ __align__(16) __half g_wp16[Cn*Cn];          // w_proj^T [N][K] fp16
__device__ __align__(16) __half g_att16[Mrows*Cn];      // attention out [B][T][H*D] fp16

// ---------------------------------------------------------------------------
// PTX helpers (sm_100-portable)
// ---------------------------------------------------------------------------
__device__ __forceinline__ uint32_t smem_to_u32(const void* p) {
    uint32_t a;
    asm("{ .reg .u64 t; cvta.to.shared.u64 t, %1; cvt.u32.u64 %0, t; }"
        : "=r"(a) : "l"(p));
    return a;
}
__device__ __forceinline__ void cp16(uint32_t dst, const void* src) {
    asm volatile("cp.async.cg.shared.global [%0], [%1], 16;"
                 :: "r"(dst), "l"(src) : "memory");
}
__device__ __forceinline__ void cp_commit() {
    asm volatile("cp.async.commit_group;" ::: "memory");
}
__device__ __forceinline__ void ldsm4(uint32_t (&r)[4], uint32_t addr) {
    asm volatile("ldmatrix.sync.aligned.m8n8.x4.shared.b16 {%0,%1,%2,%3}, [%4];"
                 : "=r"(r[0]), "=r"(r[1]), "=r"(r[2]), "=r"(r[3]) : "r"(addr));
}
__device__ __forceinline__ void mma16816h(float (&c)[4], const uint32_t (&a)[4],
                                          uint32_t b0, uint32_t b1) {
    asm volatile(
        "mma.sync.aligned.m16n8k16.row.col.f32.f16.f16.f32 "
        "{%0,%1,%2,%3}, {%4,%5,%6,%7}, {%8,%9}, {%0,%1,%2,%3};"
        : "+f"(c[0]), "+f"(c[1]), "+f"(c[2]), "+f"(c[3])
        : "r"(a[0]), "r"(a[1]), "r"(a[2]), "r"(a[3]), "r"(b0), "r"(b1));
}

// Fast exp on the FMA/ALU pipes (no MUFU), degree-4.
__device__ __forceinline__ float fexp(float x) {
    float y = x * 1.4426950408889634f;
    y = fmaxf(y, -126.0f);
    float r = y + 12582912.0f;
    float n = r - 12582912.0f;
    float f = y - n;
    int   e = __float_as_int(r);
    float u = f * 0.6931471805599453f;
    float p = 4.1666667e-2f;
    p = fmaf(p, u, 1.6666667e-1f);
    p = fmaf(p, u, 5.0e-1f);
    p = fmaf(p, u, 1.0f);
    p = fmaf(p, u, 1.0f);
    int sc = (e - 0x4B400000 + 127) << 23;
    return __int_as_float(sc) * p;
}

__device__ __forceinline__ uint32_t pack_h2(float a, float b) {
    __half2 h(__float2half(a), __float2half(b));
    return *reinterpret_cast<uint32_t*>(&h);
}

// ---------------------------------------------------------------------------
// x fp32 -> fp16
// ---------------------------------------------------------------------------
__global__ void x_to_f16(const float* __restrict__ x)
{
    int i = blockIdx.x * blockDim.x + threadIdx.x;
    if (i >= Mrows * Cn / 4) return;
    float4 v = ((const float4*)x)[i];
    *(uint32_t*)(g_x16 + (size_t)i*4)     = pack_h2(v.x, v.y);
    *(uint32_t*)(g_x16 + (size_t)i*4 + 2) = pack_h2(v.z, v.w);
}

// ---------------------------------------------------------------------------
// QKV weights (all 3 in one launch): [H][C][D] fp32 -> g_wt16 [sel][H*D][C]
// ---------------------------------------------------------------------------
__global__ void transpose_w_f16(const float* __restrict__ wq,
                                const float* __restrict__ wk,
                                const float* __restrict__ wv)
{
    __shared__ float t[32][33];
    const int sel = blockIdx.z >> 4;
    const int z   = blockIdx.z & 15;
    const float* w = (sel == 0 ? wq : (sel == 1 ? wk : wv));
    const float* src = w + (size_t)z * Cn * Dn;
    __half* dst = g_wt16 + (size_t)sel * Cn * Cn + (size_t)z * Dn * Cn;
    const int c0 = blockIdx.x * 32, r0 = blockIdx.y * 32;
    const int tx = threadIdx.x, ty = threadIdx.y;
    #pragma unroll
    for (int j = 0; j < 4; j++)
        t[ty + 8*j][tx] = src[(size_t)(r0 + ty + 8*j) * Dn + c0 + tx];
    __syncthreads();
    #pragma unroll
    for (int j = 0; j < 4; j++)
        dst[(size_t)(c0 + ty + 8*j) * Cn + r0 + tx] = __float2half(t[tx][ty + 8*j]);
}

// ---------------------------------------------------------------------------
// w_proj [C][C] fp32 -> g_wp16 [N][K] fp16 (transposed)
// ---------------------------------------------------------------------------
__global__ void transpose_wproj(const float* __restrict__ in)
{
    __shared__ float t[32][33];
    const int c0 = blockIdx.x * 32, r0 = blockIdx.y * 32;
    const int tx = threadIdx.x, ty = threadIdx.y;
    #pragma unroll
    for (int j = 0; j < 4; j++)
        t[ty + 8*j][tx] = in[(size_t)(r0 + ty + 8*j) * Cn + c0 + tx];
    __syncthreads();
    #pragma unroll
    for (int j = 0; j < 4; j++)
        g_wp16[(size_t)(c0 + ty + 8*j) * Cn + r0 + tx] = __float2half(t[tx][ty + 8*j]);
}

// ---------------------------------------------------------------------------
// V transpose: g_v [BH][T][D] fp32 -> g_vt16 [BH][D][T] fp16
// ---------------------------------------------------------------------------
__global__ void v_transpose_f16()
{
    __shared__ float t[32][33];
    const int z = blockIdx.z;
    const int t0 = blockIdx.x * 32, d0 = blockIdx.y * 32;
    const float* src = g_v + (size_t)z * Tn * Dn;
    __half* dst = g_vt16 + (size_t)z * Dn * Tn;
    const int tx = threadIdx.x, ty = threadIdx.y;
    #pragma unroll
    for (int j = 0; j < 4; j++)
        t[ty + 8*j][tx] = src[(size_t)(t0 + ty + 8*j) * Dn + d0 + tx];
    __syncthreads();
    #pragma unroll
    for (int j = 0; j < 4; j++)
        dst[(size_t)(d0 + ty + 8*j) * Tn + t0 + tx] = __float2half(t[tx][ty + 8*j]);
}

// ---------------------------------------------------------------------------
// GEMM geometry: tile 128x128, K-chunk 64, double-buffered
// ---------------------------------------------------------------------------
#define ROWB   144                // 64 fp16 (128 B) + 16 B pad
#define TILEB  (128*ROWB)         // 18432 B
#define NCHUNK (Cn/64)            // 16
#define STAGE2 (2*TILEB)          // A + B = 36864
#define GSMEM2 (2*STAGE2)         // 73728

// ---------------------------------------------------------------------------
// fp16 single-pass GEMM: C[8192,1024] = A * B^T (B stored [N][K])
// mode 0 (QKV, z=blockIdx.z): z=0 q->fp16 scaled, z=1 k->fp16, z=2 v->fp32
// mode 1 (proj): +bias -> outp fp32
// ---------------------------------------------------------------------------
__device__ __forceinline__ void load_chunk2(uint32_t sbase,
    const __half* __restrict__ Ag, const __half* __restrict__ Bg,
    int k0, int tid)
{
    const __half* gsrc[2] = {Ag, Bg};
    #pragma unroll
    for (int a = 0; a < 2; a++) {
        #pragma unroll
        for (int j = 0; j < 4; j++) {
            int o = tid + j * 256;            // 0..1023 (128 rows x 8 x 16B)
            int row = o >> 3, ch = o & 7;
            cp16(sbase + a * TILEB + row * ROWB + ch * 16,
                 gsrc[a] + (size_t)row * Cn + k0 + ch * 8);
        }
    }
}

__global__ __launch_bounds__(256) void gemm_f16(
    const float* __restrict__ bias, float* __restrict__ outp, int mode)
{
    extern __shared__ __align__(128) char smem[];
    const uint32_t smem_base = smem_to_u32(smem);
    const int tid = threadIdx.x;
    const int lane = tid & 31, wid = tid >> 5;
    const int wm = wid >> 2, wn = wid & 3;
    const int nb = blockIdx.x, mt = blockIdx.y, z = blockIdx.z;

    const __half* Ag = (mode == 0 ? g_x16 : g_att16) + (size_t)mt * 128 * Cn;
    const __half* Bg = (mode == 0 ? g_wt16 + (size_t)z * Cn * Cn : g_wp16)
                       + (size_t)nb * 128 * Cn;

    float acc[4][4][4] = {};
    const uint32_t a_row  = (lane & 15);
    const uint32_t a_kb   = (lane >> 4) << 4;
    const uint32_t b_noff = ((lane >> 4) << 3) + (lane & 7);
    const uint32_t b_kb   = ((lane >> 3) & 1) << 4;

    load_chunk2(smem_base, Ag, Bg, 0, tid);
    cp_commit();

    for (int i = 0; i < NCHUNK; i++) {
        const int buf = i & 1;
        if (i + 1 < NCHUNK) {
            load_chunk2(smem_base + (buf ^ 1) * STAGE2, Ag, Bg, (i + 1) * 64, tid);
            cp_commit();
            asm volatile("cp.async.wait_group 1;" ::: "memory");
        } else {
            asm volatile("cp.async.wait_group 0;" ::: "memory");
        }
        __syncthreads();

        const uint32_t sb = smem_base + buf * STAGE2;
        #pragma unroll
        for (int ks = 0; ks < 4; ks++) {
            uint32_t bb[2][4];
            #pragma unroll
            for (int p = 0; p < 2; p++) {
                uint32_t n = wn * 32 + p * 16 + b_noff;
                ldsm4(bb[p], sb + TILEB + n * ROWB + ks * 32 + b_kb);
            }
            #pragma unroll
            for (int mi = 0; mi < 4; mi++) {
                uint32_t r = wm * 64 + mi * 16 + a_row;
                uint32_t aa[4];
                ldsm4(aa, sb + r * ROWB + ks * 32 + a_kb);
                #pragma unroll
                for (int j = 0; j < 4; j++)
                    mma16816h(acc[mi][j], aa,
                              bb[j >> 1][(j & 1) * 2], bb[j >> 1][(j & 1) * 2 + 1]);
            }
        }
        __syncthreads();
    }

    const int lr = lane >> 2;
    const int lc = (lane & 3) * 2;
    #pragma unroll
    for (int mi = 0; mi < 4; mi++) {
        #pragma unroll
        for (int j = 0; j < 4; j++) {
            int row = mt * 128 + wm * 64 + mi * 16 + lr;
            int col = nb * 128 + wn * 32 + j * 8 + lc;
            if (mode == 1) {
                float2 bv = *(const float2*)(bias + col);
                *(float2*)(outp + (size_t)row * Cn + col) =
                    make_float2(acc[mi][j][0] + bv.x, acc[mi][j][1] + bv.y);
                *(float2*)(outp + (size_t)(row + 8) * Cn + col) =
                    make_float2(acc[mi][j][2] + bv.x, acc[mi][j][3] + bv.y);
            } else {
                int b = row >> 11, t = row & 2047;
                int h = col >> 6, d = col & 63;
                size_t off = ((size_t)((b << 4) + h) * Tn + t) * Dn + d;
                if (z == 2) {
                    *(float2*)(g_v + off) = make_float2(acc[mi][j][0], acc[mi][j][1]);
                    *(float2*)(g_v + off + 8 * Dn) = make_float2(acc[mi][j][2], acc[mi][j][3]);
                } else {
                    const float sc = (z == 0) ? 0.03125f : 1.0f;
                    __half* dst = (z == 0) ? g_q16 : g_k16;
                    *(uint32_t*)(dst + off) =
                        pack_h2(acc[mi][j][0] * sc, acc[mi][j][1] * sc);
                    *(uint32_t*)(dst + off + 8 * Dn) =
                        pack_h2(acc[mi][j][2] * sc, acc[mi][j][3] * sc);
                }
            }
        }
    }
}

// ---------------------------------------------------------------------------
// HMMA flash attention: fp16 QK, fp16 PV, FMA-pipe exp.
// Grid (T/128, B*H); heavy (high-qt) tiles scheduled FIRST for wave packing.
// ---------------------------------------------------------------------------
#define AT_PITCH 144
#define AT_TILE  (64*AT_PITCH)       // 9216
#define AT_STAGE (2*AT_TILE)         // 18432: Kf, Vf
#define AT_SMEM  (2*AT_STAGE)        // 36864

__device__ __forceinline__ void at_load_kv(uint32_t dstbase,
    const __half* __restrict__ Kf, const __half* __restrict__ Vtf,
    int jt, int tid)
{
    const int koff = jt * 64;
    #pragma unroll
    for (int i = 0; i < 4; i++) {
        int c = tid + i * 256;           // 0..1023
        int arr = c >> 9;                // 0..1
        int cc = c & 511;
        int row = cc >> 3, o = cc & 7;
        const void* g = arr ? (const void*)(Vtf + (size_t)row * Tn + koff + o * 8)
                            : (const void*)(Kf + (size_t)(koff + row) * Dn + o * 8);
        cp16(dstbase + arr * AT_TILE + row * AT_PITCH + o * 16, g);
    }
}

__global__ __launch_bounds__(256, 1) void attn_mma()
{
    extern __shared__ __align__(128) char smem[];
    const uint32_t sb = smem_to_u32(smem);
    const int tid = threadIdx.x;
    const int lane = tid & 31, wid = tid >> 5;
    const int qt = (gridDim.x - 1) - blockIdx.x;   // heavy tiles first
    const int bh = blockIdx.y;
    const int b = bh >> 4, h = bh & 15;

    const __half* Qf  = g_q16 + ((size_t)bh * Tn + qt * 128) * Dn;
    const __half* Kf  = g_k16 + (size_t)bh * Tn * Dn;
    const __half* Vtf = g_vt16 + (size_t)bh * Dn * Tn;

    // stage Q (128 x 64 fp16) into smem, ldmatrix into registers
    #pragma unroll
    for (int i = 0; i < 4; i++) {
        int c = tid + i * 256;
        int row = c >> 3, o = c & 7;
        cp16(sb + row * AT_PITCH + o * 16, Qf + (size_t)row * Dn + o * 8);
    }
    cp_commit();
    asm volatile("cp.async.wait_group 0;" ::: "memory");
    __syncthreads();

    uint32_t qf[4][4];
    {
        uint32_t abase = sb + (wid * 16 + (lane & 15)) * AT_PITCH + ((lane >> 4) << 4);
        #pragma unroll
        for (int kk = 0; kk < 4; kk++)
            ldsm4(qf[kk], abase + kk * 32);
    }
    __syncthreads();

    const uint32_t b_noff = ((lane >> 4) << 3) + (lane & 7);
    const uint32_t b_kb   = ((lane >> 3) & 1) << 4;

    float o_[8][4] = {};
    float m0 = -1e30f, m1 = -1e30f, l0 = 0.0f, l1 = 0.0f;

    const int jmax = 2 * qt + 1;
    at_load_kv(sb, Kf, Vtf, 0, tid);
    cp_commit();

    for (int jt = 0; jt <= jmax; jt++) {
        const int stg = jt & 1;
        if (jt < jmax) {
            at_load_kv(sb + (stg ^ 1) * AT_STAGE, Kf, Vtf, jt + 1, tid);
            cp_commit();
            asm volatile("cp.async.wait_group 1;" ::: "memory");
        } else {
            asm volatile("cp.async.wait_group 0;" ::: "memory");
        }
        __syncthreads();

        const uint32_t s0 = sb + stg * AT_STAGE;

        // ---- S = Q @ K^T (fp16) ----
        float s[8][4];
        #pragma unroll
        for (int j = 0; j < 8; j++)
            #pragma unroll
            for (int c = 0; c < 4; c++) s[j][c] = 0.0f;

        #pragma unroll
        for (int j = 0; j < 4; j++) {
            #pragma unroll
            for (int kk = 0; kk < 4; kk++) {
                uint32_t kf4[4];
                ldsm4(kf4, s0 + (j * 16 + b_noff) * AT_PITCH + kk * 32 + b_kb);
                mma16816h(s[2*j],   qf[kk], kf4[0], kf4[1]);
                mma16816h(s[2*j+1], qf[kk], kf4[2], kf4[3]);
            }
        }

        // ---- causal mask ----
        const int r0 = qt * 128 + wid * 16 + (lane >> 2);
        const int r1 = r0 + 8;
        if (jt >= 2 * qt) {
            #pragma unroll
            for (int j = 0; j < 8; j++) {
                int kc = jt * 64 + j * 8 + 2 * (lane & 3);
                if (kc     > r0) s[j][0] = -1e30f;
                if (kc + 1 > r0) s[j][1] = -1e30f;
                if (kc     > r1) s[j][2] = -1e30f;
                if (kc + 1 > r1) s[j][3] = -1e30f;
            }
        }

        // ---- online softmax ----
        float mt0 = -1e30f, mt1 = -1e30f;
        #pragma unroll
        for (int j = 0; j < 8; j++) {
            mt0 = fmaxf(mt0, fmaxf(s[j][0], s[j][1]));
            mt1 = fmaxf(mt1, fmaxf(s[j][2], s[j][3]));
        }
        mt0 = fmaxf(mt0, __shfl_xor_sync(0xffffffffu, mt0, 1));
        mt0 = fmaxf(mt0, __shfl_xor_sync(0xffffffffu, mt0, 2));
        mt1 = fmaxf(mt1, __shfl_xor_sync(0xffffffffu, mt1, 1));
        mt1 = fmaxf(mt1, __shfl_xor_sync(0xffffffffu, mt1, 2));

        float mn0 = fmaxf(m0, mt0), mn1 = fmaxf(m1, mt1);
        float al0 = fexp(m0 - mn0), al1 = fexp(m1 - mn1);
        m0 = mn0; m1 = mn1;
        l0 *= al0; l1 *= al1;
        #pragma unroll
        for (int j = 0; j < 8; j++) {
            o_[j][0] *= al0; o_[j][1] *= al0;
            o_[j][2] *= al1; o_[j][3] *= al1;
        }
        float rs0 = 0.0f, rs1 = 0.0f;
        #pragma unroll
        for (int j = 0; j < 8; j++) {
            s[j][0] = fexp(s[j][0] - mn0); rs0 += s[j][0];
            s[j][1] = fexp(s[j][1] - mn0); rs0 += s[j][1];
            s[j][2] = fexp(s[j][2] - mn1); rs1 += s[j][2];
            s[j][3] = fexp(s[j][3] - mn1); rs1 += s[j][3];
        }
        rs0 += __shfl_xor_sync(0xffffffffu, rs0, 1);
        rs0 += __shfl_xor_sync(0xffffffffu, rs0, 2);
        rs1 += __shfl_xor_sync(0xffffffffu, rs1, 1);
        rs1 += __shfl_xor_sync(0xffffffffu, rs1, 2);
        l0 += rs0; l1 += rs1;

        // ---- pack P fp16 A-fragments ----
        uint32_t pf[4][4];
        #pragma unroll
        for (int kk = 0; kk < 4; kk++) {
            pf[kk][0] = pack_h2(s[2*kk][0],   s[2*kk][1]);
            pf[kk][1] = pack_h2(s[2*kk][2],   s[2*kk][3]);
            pf[kk][2] = pack_h2(s[2*kk+1][0], s[2*kk+1][1]);
            pf[kk][3] = pack_h2(s[2*kk+1][2], s[2*kk+1][3]);
        }

        // ---- O += P @ V (fp16) ----
        #pragma unroll
        for (int jd = 0; jd < 4; jd++) {
            #pragma unroll
            for (int kk = 0; kk < 4; kk++) {
                uint32_t vf4[4];
                ldsm4(vf4, s0 + AT_TILE + (jd * 16 + b_noff) * AT_PITCH
                           + kk * 32 + b_kb);
                mma16816h(o_[2*jd],   pf[kk], vf4[0], vf4[1]);
                mma16816h(o_[2*jd+1], pf[kk], vf4[2], vf4[3]);
            }
        }
        __syncthreads();
    }

    // epilogue: normalize + write att fp16 [B][T][H*D]
    const float inv0 = 1.0f / l0, inv1 = 1.0f / l1;
    const int r0 = qt * 128 + wid * 16 + (lane >> 2);
    size_t off = ((size_t)b * Tn + r0) * Cn + h * 64;
    #pragma unroll
    for (int j = 0; j < 8; j++) {
        int d = j * 8 + 2 * (lane & 3);
        *(uint32_t*)(g_att16 + off + d) = pack_h2(o_[j][0] * inv0, o_[j][1] * inv0);
        *(uint32_t*)(g_att16 + off + 8 * Cn + d) = pack_h2(o_[j][2] * inv1, o_[j][3] * inv1);
    }
}

// ---------------------------------------------------------------------------
extern "C" void kernel_launch(void* const* d_in, const int* in_sizes, int n_in,
                              void* d_out, int out_size)
{
    const float* x      = (const float*)d_in[0];
    const float* wq     = (const float*)d_in[1];
    const float* wk     = (const float*)d_in[2];
    const float* wv     = (const float*)d_in[3];
    const float* w_proj = (const float*)d_in[4];
    const float* b_proj = (const float*)d_in[5];
    float* out = (float*)d_out;

    cudaFuncSetAttribute(gemm_f16,
                         cudaFuncAttributeMaxDynamicSharedMemorySize, GSMEM2);

    // 1) x -> fp16
    int n4 = Mrows * Cn / 4;
    x_to_f16<<<(n4 + 255) / 256, 256>>>(x);

    // 2) weights -> fp16 transposed
    transpose_w_f16<<<dim3(Dn/32, Cn/32, 3*Hn), dim3(32,8)>>>(wq, wk, wv);
    transpose_wproj<<<dim3(Cn/32, Cn/32), dim3(32,8)>>>(w_proj);

    // 3) QKV GEMM (fp16; q/k -> fp16, v -> fp32)
    gemm_f16<<<dim3(Cn/128, Mrows/128, 3), 256, GSMEM2>>>(nullptr, nullptr, 0);

    // 4) V transpose (fp16)
    v_transpose_f16<<<dim3(Tn/32, Dn/32, Bn*Hn), dim3(32,8)>>>();

    // 5) attention (fp16 QK + fp16 PV)
    attn_mma<<<dim3(Tn/128, Bn*Hn), 256, AT_SMEM>>>();

    // 6) output projection (fp16, +bias)
    gemm_f16<<<dim3(Cn/128, Mrows/128, 1), 256, GSMEM2>>>(b_proj, out, 1);
}